// round 1
// baseline (speedup 1.0000x reference)
#include <cuda_runtime.h>
#include <cuda_bf16.h>

#define BB 16
#define SS 512
#define DD 512
#define HH 8
#define DHH 64
#define EPSF 1e-5f
#define NEGF -1.0e9f

// ---------------- scratch (device globals; no allocations allowed) ----------
__device__ float g_h[BB * SS * DD];            // 16 MB  LN output
__device__ float g_q[BB * HH * SS * DHH];      // 16 MB  [B,H,S,DH]
__device__ float g_k[BB * HH * SS * DHH];
__device__ float g_v[BB * HH * SS * DHH];
__device__ float g_scores[BB * HH * SS * SS];  // 128 MB [B,H,S,S]
__device__ float g_ao[BB * SS * DD];           // 16 MB  attn@V back in [B,S,D]

// ---------------- kernel 1: pre-LayerNorm over x rows (len 512) -------------
__global__ void __launch_bounds__(256) ln_kernel(const float* __restrict__ x,
                                                 const float* __restrict__ g,
                                                 const float* __restrict__ b,
                                                 float* __restrict__ out) {
    int row = blockIdx.x;
    const float* xr = x + (size_t)row * DD;
    int t = threadIdx.x;
    float v0 = xr[t], v1 = xr[t + 256];
    __shared__ float s1[256], s2[256];
    s1[t] = v0 + v1;
    s2[t] = v0 * v0 + v1 * v1;
    __syncthreads();
    for (int o = 128; o > 0; o >>= 1) {
        if (t < o) { s1[t] += s1[t + o]; s2[t] += s2[t + o]; }
        __syncthreads();
    }
    float mu  = s1[0] * (1.0f / DD);
    float var = s2[0] * (1.0f / DD) - mu * mu;
    float inv = rsqrtf(var + EPSF);
    out[(size_t)row * DD + t]       = (v0 - mu) * inv * g[t] + b[t];
    out[(size_t)row * DD + t + 256] = (v1 - mu) * inv * g[t + 256] + b[t + 256];
}

// ---------------- kernel 2: QKV projection GEMM ------------------------------
// C[8192,512] = A[8192,512] @ W[512,512] + bias, output scattered to [B,H,S,DH]
__global__ void __launch_bounds__(256) gemm_qkv(const float* __restrict__ A,
                                                const float* __restrict__ W,
                                                const float* __restrict__ bias,
                                                float* __restrict__ out) {
    __shared__ float As[16][128];
    __shared__ float Bs[16][128];
    int tid = threadIdx.x;
    int tx = tid & 15, ty = tid >> 4;
    int m0 = blockIdx.y * 128;
    int n0 = blockIdx.x * 128;
    float acc[8][8] = {};
    int arow = tid >> 2;            // 0..63
    int acol = (tid & 3) * 4;       // 0,4,8,12
    int brow = tid >> 5;            // 0..7
    int bcol = (tid & 31) * 4;      // 0..124
    for (int kt = 0; kt < 512; kt += 16) {
        #pragma unroll
        for (int i = 0; i < 2; i++) {
            int r = arow + i * 64;
            float4 v = *(const float4*)(A + (size_t)(m0 + r) * 512 + kt + acol);
            As[acol + 0][r] = v.x; As[acol + 1][r] = v.y;
            As[acol + 2][r] = v.z; As[acol + 3][r] = v.w;
        }
        #pragma unroll
        for (int i = 0; i < 2; i++) {
            int r = brow + i * 8;
            float4 v = *(const float4*)(W + (size_t)(kt + r) * 512 + n0 + bcol);
            *(float4*)&Bs[r][bcol] = v;
        }
        __syncthreads();
        #pragma unroll
        for (int kk = 0; kk < 16; kk++) {
            float a[8], bv[8];
            #pragma unroll
            for (int i = 0; i < 8; i++) a[i] = As[kk][ty * 8 + i];
            #pragma unroll
            for (int j = 0; j < 8; j++) bv[j] = Bs[kk][tx * 8 + j];
            #pragma unroll
            for (int i = 0; i < 8; i++)
                #pragma unroll
                for (int j = 0; j < 8; j++)
                    acc[i][j] += a[i] * bv[j];
        }
        __syncthreads();
    }
    #pragma unroll
    for (int i = 0; i < 8; i++) {
        int m = m0 + ty * 8 + i;
        int b_ = m >> 9;
        int s  = m & 511;
        #pragma unroll
        for (int j = 0; j < 8; j++) {
            int n = n0 + tx * 8 + j;
            int hh = n >> 6, dh = n & 63;
            out[(size_t)(((b_ * HH + hh) * SS + s)) * DHH + dh] = acc[i][j] + bias[n];
        }
    }
}

// ---------------- kernel 3: scores = Q @ K^T / sqrt(DH) ----------------------
// per (b,h): [512,64] x [512,64]^T -> [512,512]
__global__ void __launch_bounds__(256) scores_kernel(const float* __restrict__ Q,
                                                     const float* __restrict__ K,
                                                     float* __restrict__ scores) {
    __shared__ float Qs[64][68];
    __shared__ float Ks[64][68];
    int bh = blockIdx.z;
    int q0 = blockIdx.y * 64;
    int k0 = blockIdx.x * 64;
    const float* Qb = Q + (size_t)bh * SS * DHH;
    const float* Kb = K + (size_t)bh * SS * DHH;
    int tid = threadIdx.x;
    int tx = tid & 15, ty = tid >> 4;
    // load: thread handles row = tid/16 (+16 stride), dh group = (tid%16)*4
    int lrow = tid >> 4;            // 0..15
    int ldh  = (tid & 15) * 4;      // 0..60
    #pragma unroll
    for (int i = 0; i < 4; i++) {
        int r = lrow + i * 16;
        float4 vq = *(const float4*)(Qb + (size_t)(q0 + r) * DHH + ldh);
        Qs[ldh + 0][r] = vq.x; Qs[ldh + 1][r] = vq.y;
        Qs[ldh + 2][r] = vq.z; Qs[ldh + 3][r] = vq.w;
        float4 vk = *(const float4*)(Kb + (size_t)(k0 + r) * DHH + ldh);
        Ks[ldh + 0][r] = vk.x; Ks[ldh + 1][r] = vk.y;
        Ks[ldh + 2][r] = vk.z; Ks[ldh + 3][r] = vk.w;
    }
    __syncthreads();
    float acc[4][4] = {};
    #pragma unroll
    for (int kk = 0; kk < 64; kk++) {
        float a[4], bv[4];
        #pragma unroll
        for (int i = 0; i < 4; i++) a[i] = Qs[kk][ty * 4 + i];
        #pragma unroll
        for (int j = 0; j < 4; j++) bv[j] = Ks[kk][tx * 4 + j];
        #pragma unroll
        for (int i = 0; i < 4; i++)
            #pragma unroll
            for (int j = 0; j < 4; j++)
                acc[i][j] += a[i] * bv[j];
    }
    float* srow = scores + (size_t)bh * SS * SS;
    #pragma unroll
    for (int i = 0; i < 4; i++) {
        int qq = q0 + ty * 4 + i;
        #pragma unroll
        for (int j = 0; j < 4; j++) {
            srow[(size_t)qq * SS + k0 + tx * 4 + j] = acc[i][j] * 0.125f;
        }
    }
}

// ---------------- kernel 4: fused score-LN + mask + softmax (in place) -------
__global__ void __launch_bounds__(256) lnsoftmax_kernel(float* __restrict__ scores,
                                                        const int* __restrict__ mask,
                                                        const float* __restrict__ lg,
                                                        const float* __restrict__ lb) {
    int r = blockIdx.x;                    // 0..B*H*S-1
    int b_ = r / (HH * SS);
    int q  = r & (SS - 1);
    float* row = scores + (size_t)r * SS;
    const int* mrow = mask + ((size_t)b_ * SS + q) * SS;
    int t = threadIdx.x;
    float v0 = row[t], v1 = row[t + 256];
    __shared__ float s1[256], s2[256];
    s1[t] = v0 + v1;
    s2[t] = v0 * v0 + v1 * v1;
    __syncthreads();
    for (int o = 128; o > 0; o >>= 1) {
        if (t < o) { s1[t] += s1[t + o]; s2[t] += s2[t + o]; }
        __syncthreads();
    }
    float mu  = s1[0] * (1.0f / SS);
    float var = s2[0] * (1.0f / SS) - mu * mu;
    float inv = rsqrtf(var + EPSF);
    v0 = (v0 - mu) * inv * lg[t] + lb[t];
    v1 = (v1 - mu) * inv * lg[t + 256] + lb[t + 256];
    if (mrow[t] == 0)       v0 = NEGF;
    if (mrow[t + 256] == 0) v1 = NEGF;
    __syncthreads();
    s1[t] = fmaxf(v0, v1);
    __syncthreads();
    for (int o = 128; o > 0; o >>= 1) {
        if (t < o) s1[t] = fmaxf(s1[t], s1[t + o]);
        __syncthreads();
    }
    float mx = s1[0];
    v0 = __expf(v0 - mx);
    v1 = __expf(v1 - mx);
    __syncthreads();
    s1[t] = v0 + v1;
    __syncthreads();
    for (int o = 128; o > 0; o >>= 1) {
        if (t < o) s1[t] += s1[t + o];
        __syncthreads();
    }
    float rs = 1.0f / s1[0];
    row[t]       = v0 * rs;
    row[t + 256] = v1 * rs;
}

// ---------------- kernel 5: attn @ V -----------------------------------------
// per (b,h): [512,512] x [512,64] -> [512,64], scattered to [B,S,D]
__global__ void __launch_bounds__(256) av_kernel(const float* __restrict__ P,
                                                 const float* __restrict__ V,
                                                 float* __restrict__ out) {
    __shared__ float As[32][68];
    __shared__ float Bs[32][68];
    int bh = blockIdx.y;
    int b_ = bh / HH, hh = bh % HH;
    int m0 = blockIdx.x * 64;
    const float* Pb = P + (size_t)bh * SS * SS;
    const float* Vb = V + (size_t)bh * SS * DHH;
    int tid = threadIdx.x;
    int tx = tid & 15, ty = tid >> 4;
    int amrow = tid >> 3;           // 0..31
    int akcol = (tid & 7) * 4;      // 0..28
    int bkrow = tid >> 4;           // 0..15
    int bncol = (tid & 15) * 4;     // 0..60
    float acc[4][4] = {};
    for (int kt = 0; kt < 512; kt += 32) {
        #pragma unroll
        for (int i = 0; i < 2; i++) {
            int r = amrow + i * 32;
            float4 v = *(const float4*)(Pb + (size_t)(m0 + r) * SS + kt + akcol);
            As[akcol + 0][r] = v.x; As[akcol + 1][r] = v.y;
            As[akcol + 2][r] = v.z; As[akcol + 3][r] = v.w;
        }
        #pragma unroll
        for (int i = 0; i < 2; i++) {
            int r = bkrow + i * 16;
            float4 v = *(const float4*)(Vb + (size_t)(kt + r) * DHH + bncol);
            *(float4*)&Bs[r][bncol] = v;
        }
        __syncthreads();
        #pragma unroll
        for (int kk = 0; kk < 32; kk++) {
            float a[4], bv[4];
            #pragma unroll
            for (int i = 0; i < 4; i++) a[i] = As[kk][ty * 4 + i];
            #pragma unroll
            for (int j = 0; j < 4; j++) bv[j] = Bs[kk][tx * 4 + j];
            #pragma unroll
            for (int i = 0; i < 4; i++)
                #pragma unroll
                for (int j = 0; j < 4; j++)
                    acc[i][j] += a[i] * bv[j];
        }
        __syncthreads();
    }
    #pragma unroll
    for (int i = 0; i < 4; i++) {
        int s = m0 + ty * 4 + i;
        #pragma unroll
        for (int j = 0; j < 4; j++) {
            int n = tx * 4 + j;
            out[((size_t)(b_ * SS + s)) * DD + hh * DHH + n] = acc[i][j];
        }
    }
}

// ---------------- kernel 6: output projection + bias + residual --------------
__global__ void __launch_bounds__(256) gemm_out(const float* __restrict__ A,
                                                const float* __restrict__ W,
                                                const float* __restrict__ bias,
                                                const float* __restrict__ x,
                                                float* __restrict__ out) {
    __shared__ float As[16][128];
    __shared__ float Bs[16][128];
    int tid = threadIdx.x;
    int tx = tid & 15, ty = tid >> 4;
    int m0 = blockIdx.y * 128;
    int n0 = blockIdx.x * 128;
    float acc[8][8] = {};
    int arow = tid >> 2;
    int acol = (tid & 3) * 4;
    int brow = tid >> 5;
    int bcol = (tid & 31) * 4;
    for (int kt = 0; kt < 512; kt += 16) {
        #pragma unroll
        for (int i = 0; i < 2; i++) {
            int r = arow + i * 64;
            float4 v = *(const float4*)(A + (size_t)(m0 + r) * 512 + kt + acol);
            As[acol + 0][r] = v.x; As[acol + 1][r] = v.y;
            As[acol + 2][r] = v.z; As[acol + 3][r] = v.w;
        }
        #pragma unroll
        for (int i = 0; i < 2; i++) {
            int r = brow + i * 8;
            float4 v = *(const float4*)(W + (size_t)(kt + r) * 512 + n0 + bcol);
            *(float4*)&Bs[r][bcol] = v;
        }
        __syncthreads();
        #pragma unroll
        for (int kk = 0; kk < 16; kk++) {
            float a[8], bv[8];
            #pragma unroll
            for (int i = 0; i < 8; i++) a[i] = As[kk][ty * 8 + i];
            #pragma unroll
            for (int j = 0; j < 8; j++) bv[j] = Bs[kk][tx * 8 + j];
            #pragma unroll
            for (int i = 0; i < 8; i++)
                #pragma unroll
                for (int j = 0; j < 8; j++)
                    acc[i][j] += a[i] * bv[j];
        }
        __syncthreads();
    }
    #pragma unroll
    for (int i = 0; i < 8; i++) {
        int m = m0 + ty * 8 + i;
        #pragma unroll
        for (int j = 0; j < 8; j++) {
            int n = n0 + tx * 8 + j;
            out[(size_t)m * 512 + n] = acc[i][j] + bias[n] + x[(size_t)m * 512 + n];
        }
    }
}

// ---------------- host launcher ----------------------------------------------
extern "C" void kernel_launch(void* const* d_in, const int* in_sizes, int n_in,
                              void* d_out, int out_size) {
    const float* x    = (const float*)d_in[0];
    const int*   mask = (const int*)  d_in[1];
    const float* ln_g = (const float*)d_in[2];
    const float* ln_b = (const float*)d_in[3];
    const float* lna_g= (const float*)d_in[4];
    const float* lna_b= (const float*)d_in[5];
    const float* Wq   = (const float*)d_in[6];
    const float* bq   = (const float*)d_in[7];
    const float* Wk   = (const float*)d_in[8];
    const float* bk   = (const float*)d_in[9];
    const float* Wv   = (const float*)d_in[10];
    const float* bv   = (const float*)d_in[11];
    const float* Wd   = (const float*)d_in[12];
    const float* bd   = (const float*)d_in[13];
    float* out = (float*)d_out;

    float *h, *q, *k, *v, *scores, *ao;
    cudaGetSymbolAddress((void**)&h,      g_h);
    cudaGetSymbolAddress((void**)&q,      g_q);
    cudaGetSymbolAddress((void**)&k,      g_k);
    cudaGetSymbolAddress((void**)&v,      g_v);
    cudaGetSymbolAddress((void**)&scores, g_scores);
    cudaGetSymbolAddress((void**)&ao,     g_ao);

    // 1. pre-LN
    ln_kernel<<<BB * SS, 256>>>(x, ln_g, ln_b, h);
    // 2. QKV projections -> [B,H,S,DH]
    dim3 ggrid(4, 64);
    gemm_qkv<<<ggrid, 256>>>(h, Wq, bq, q);
    gemm_qkv<<<ggrid, 256>>>(h, Wk, bk, k);
    gemm_qkv<<<ggrid, 256>>>(h, Wv, bv, v);
    // 3. scores = Q K^T / 8
    dim3 sgrid(8, 8, BB * HH);
    scores_kernel<<<sgrid, 256>>>(q, k, scores);
    // 4. LN over key axis + mask + softmax (in place)
    lnsoftmax_kernel<<<BB * HH * SS, 256>>>(scores, mask, lna_g, lna_b);
    // 5. attn @ V -> [B,S,D]
    dim3 avgrid(8, BB * HH);
    av_kernel<<<avgrid, 256>>>(scores, v, ao);
    // 6. output projection + residual
    gemm_out<<<ggrid, 256>>>(ao, Wd, bd, x, out);
}

// round 7
// speedup vs baseline: 1.0005x; 1.0005x over previous
#include <cuda_runtime.h>
#include <cuda_bf16.h>

#define BB 16
#define SS 512
#define DD 512
#define HH 8
#define DHH 64
#define EPSF 1e-5f
#define NEGF -1.0e9f

// ---------------- scratch (device globals; no allocations allowed) ----------
__device__ float g_h[BB * SS * DD];            // 16 MB  LN output
__device__ float g_q[BB * HH * SS * DHH];      // 16 MB  [B,H,S,DH]
__device__ float g_k[BB * HH * SS * DHH];
__device__ float g_v[BB * HH * SS * DHH];
__device__ float g_scores[BB * HH * SS * SS];  // 128 MB [B,H,S,S]
__device__ float g_ao[BB * SS * DD];           // 16 MB  attn@V back in [B,S,D]

// ---------------- kernel 1: pre-LayerNorm over x rows (len 512) -------------
__global__ void __launch_bounds__(256) ln_kernel(const float* __restrict__ x,
                                                 const float* __restrict__ g,
                                                 const float* __restrict__ b,
                                                 float* __restrict__ out) {
    int row = blockIdx.x;
    const float* xr = x + (size_t)row * DD;
    int t = threadIdx.x;
    float v0 = xr[t], v1 = xr[t + 256];
    __shared__ float s1[256], s2[256];
    s1[t] = v0 + v1;
    s2[t] = v0 * v0 + v1 * v1;
    __syncthreads();
    for (int o = 128; o > 0; o >>= 1) {
        if (t < o) { s1[t] += s1[t + o]; s2[t] += s2[t + o]; }
        __syncthreads();
    }
    float mu  = s1[0] * (1.0f / DD);
    float var = s2[0] * (1.0f / DD) - mu * mu;
    float inv = rsqrtf(var + EPSF);
    out[(size_t)row * DD + t]       = (v0 - mu) * inv * g[t] + b[t];
    out[(size_t)row * DD + t + 256] = (v1 - mu) * inv * g[t + 256] + b[t + 256];
}

// ---------------- kernel 2: QKV projection GEMM ------------------------------
// C[8192,512] = A[8192,512] @ W[512,512] + bias, output scattered to [B,H,S,DH]
__global__ void __launch_bounds__(256) gemm_qkv(const float* __restrict__ A,
                                                const float* __restrict__ W,
                                                const float* __restrict__ bias,
                                                float* __restrict__ out) {
    __shared__ float As[16][128];
    __shared__ float Bs[16][128];
    int tid = threadIdx.x;
    int tx = tid & 15, ty = tid >> 4;
    int m0 = blockIdx.y * 128;
    int n0 = blockIdx.x * 128;
    float acc[8][8] = {};
    int arow = tid >> 2;            // 0..63
    int acol = (tid & 3) * 4;       // 0,4,8,12
    int brow = tid >> 5;            // 0..7
    int bcol = (tid & 31) * 4;      // 0..124
    for (int kt = 0; kt < 512; kt += 16) {
        #pragma unroll
        for (int i = 0; i < 2; i++) {
            int r = arow + i * 64;
            float4 v = *(const float4*)(A + (size_t)(m0 + r) * 512 + kt + acol);
            As[acol + 0][r] = v.x; As[acol + 1][r] = v.y;
            As[acol + 2][r] = v.z; As[acol + 3][r] = v.w;
        }
        #pragma unroll
        for (int i = 0; i < 2; i++) {
            int r = brow + i * 8;
            float4 v = *(const float4*)(W + (size_t)(kt + r) * 512 + n0 + bcol);
            *(float4*)&Bs[r][bcol] = v;
        }
        __syncthreads();
        #pragma unroll
        for (int kk = 0; kk < 16; kk++) {
            float a[8], bv[8];
            #pragma unroll
            for (int i = 0; i < 8; i++) a[i] = As[kk][ty * 8 + i];
            #pragma unroll
            for (int j = 0; j < 8; j++) bv[j] = Bs[kk][tx * 8 + j];
            #pragma unroll
            for (int i = 0; i < 8; i++)
                #pragma unroll
                for (int j = 0; j < 8; j++)
                    acc[i][j] += a[i] * bv[j];
        }
        __syncthreads();
    }
    #pragma unroll
    for (int i = 0; i < 8; i++) {
        int m = m0 + ty * 8 + i;
        int b_ = m >> 9;
        int s  = m & 511;
        #pragma unroll
        for (int j = 0; j < 8; j++) {
            int n = n0 + tx * 8 + j;
            int hh = n >> 6, dh = n & 63;
            out[(size_t)(((b_ * HH + hh) * SS + s)) * DHH + dh] = acc[i][j] + bias[n];
        }
    }
}

// ---------------- kernel 3: scores = Q @ K^T / sqrt(DH) ----------------------
// per (b,h): [512,64] x [512,64]^T -> [512,512]
__global__ void __launch_bounds__(256) scores_kernel(const float* __restrict__ Q,
                                                     const float* __restrict__ K,
                                                     float* __restrict__ scores) {
    __shared__ float Qs[64][68];
    __shared__ float Ks[64][68];
    int bh = blockIdx.z;
    int q0 = blockIdx.y * 64;
    int k0 = blockIdx.x * 64;
    const float* Qb = Q + (size_t)bh * SS * DHH;
    const float* Kb = K + (size_t)bh * SS * DHH;
    int tid = threadIdx.x;
    int tx = tid & 15, ty = tid >> 4;
    // load: thread handles row = tid/16 (+16 stride), dh group = (tid%16)*4
    int lrow = tid >> 4;            // 0..15
    int ldh  = (tid & 15) * 4;      // 0..60
    #pragma unroll
    for (int i = 0; i < 4; i++) {
        int r = lrow + i * 16;
        float4 vq = *(const float4*)(Qb + (size_t)(q0 + r) * DHH + ldh);
        Qs[ldh + 0][r] = vq.x; Qs[ldh + 1][r] = vq.y;
        Qs[ldh + 2][r] = vq.z; Qs[ldh + 3][r] = vq.w;
        float4 vk = *(const float4*)(Kb + (size_t)(k0 + r) * DHH + ldh);
        Ks[ldh + 0][r] = vk.x; Ks[ldh + 1][r] = vk.y;
        Ks[ldh + 2][r] = vk.z; Ks[ldh + 3][r] = vk.w;
    }
    __syncthreads();
    float acc[4][4] = {};
    #pragma unroll
    for (int kk = 0; kk < 64; kk++) {
        float a[4], bv[4];
        #pragma unroll
        for (int i = 0; i < 4; i++) a[i] = Qs[kk][ty * 4 + i];
        #pragma unroll
        for (int j = 0; j < 4; j++) bv[j] = Ks[kk][tx * 4 + j];
        #pragma unroll
        for (int i = 0; i < 4; i++)
            #pragma unroll
            for (int j = 0; j < 4; j++)
                acc[i][j] += a[i] * bv[j];
    }
    float* srow = scores + (size_t)bh * SS * SS;
    #pragma unroll
    for (int i = 0; i < 4; i++) {
        int qq = q0 + ty * 4 + i;
        #pragma unroll
        for (int j = 0; j < 4; j++) {
            srow[(size_t)qq * SS + k0 + tx * 4 + j] = acc[i][j] * 0.125f;
        }
    }
}

// ---------------- kernel 4: fused score-LN + mask + softmax (in place) -------
__global__ void __launch_bounds__(256) lnsoftmax_kernel(float* __restrict__ scores,
                                                        const int* __restrict__ mask,
                                                        const float* __restrict__ lg,
                                                        const float* __restrict__ lb) {
    int r = blockIdx.x;                    // 0..B*H*S-1
    int b_ = r / (HH * SS);
    int q  = r & (SS - 1);
    float* row = scores + (size_t)r * SS;
    const int* mrow = mask + ((size_t)b_ * SS + q) * SS;
    int t = threadIdx.x;
    float v0 = row[t], v1 = row[t + 256];
    __shared__ float s1[256], s2[256];
    s1[t] = v0 + v1;
    s2[t] = v0 * v0 + v1 * v1;
    __syncthreads();
    for (int o = 128; o > 0; o >>= 1) {
        if (t < o) { s1[t] += s1[t + o]; s2[t] += s2[t + o]; }
        __syncthreads();
    }
    float mu  = s1[0] * (1.0f / SS);
    float var = s2[0] * (1.0f / SS) - mu * mu;
    float inv = rsqrtf(var + EPSF);
    v0 = (v0 - mu) * inv * lg[t] + lb[t];
    v1 = (v1 - mu) * inv * lg[t + 256] + lb[t + 256];
    if (mrow[t] == 0)       v0 = NEGF;
    if (mrow[t + 256] == 0) v1 = NEGF;
    __syncthreads();
    s1[t] = fmaxf(v0, v1);
    __syncthreads();
    for (int o = 128; o > 0; o >>= 1) {
        if (t < o) s1[t] = fmaxf(s1[t], s1[t + o]);
        __syncthreads();
    }
    float mx = s1[0];
    v0 = __expf(v0 - mx);
    v1 = __expf(v1 - mx);
    __syncthreads();
    s1[t] = v0 + v1;
    __syncthreads();
    for (int o = 128; o > 0; o >>= 1) {
        if (t < o) s1[t] += s1[t + o];
        __syncthreads();
    }
    float rs = 1.0f / s1[0];
    row[t]       = v0 * rs;
    row[t + 256] = v1 * rs;
}

// ---------------- kernel 5: attn @ V -----------------------------------------
// per (b,h): [512,512] x [512,64] -> [512,64], scattered to [B,S,D]
__global__ void __launch_bounds__(256) av_kernel(const float* __restrict__ P,
                                                 const float* __restrict__ V,
                                                 float* __restrict__ out) {
    __shared__ float As[32][68];
    __shared__ float Bs[32][68];
    int bh = blockIdx.y;
    int b_ = bh / HH, hh = bh % HH;
    int m0 = blockIdx.x * 64;
    const float* Pb = P + (size_t)bh * SS * SS;
    const float* Vb = V + (size_t)bh * SS * DHH;
    int tid = threadIdx.x;
    int tx = tid & 15, ty = tid >> 4;
    int amrow = tid >> 3;           // 0..31
    int akcol = (tid & 7) * 4;      // 0..28
    int bkrow = tid >> 4;           // 0..15
    int bncol = (tid & 15) * 4;     // 0..60
    float acc[4][4] = {};
    for (int kt = 0; kt < 512; kt += 32) {
        #pragma unroll
        for (int i = 0; i < 2; i++) {
            int r = amrow + i * 32;
            float4 v = *(const float4*)(Pb + (size_t)(m0 + r) * SS + kt + akcol);
            As[akcol + 0][r] = v.x; As[akcol + 1][r] = v.y;
            As[akcol + 2][r] = v.z; As[akcol + 3][r] = v.w;
        }
        #pragma unroll
        for (int i = 0; i < 2; i++) {
            int r = bkrow + i * 16;
            float4 v = *(const float4*)(Vb + (size_t)(kt + r) * DHH + bncol);
            *(float4*)&Bs[r][bncol] = v;
        }
        __syncthreads();
        #pragma unroll
        for (int kk = 0; kk < 32; kk++) {
            float a[4], bv[4];
            #pragma unroll
            for (int i = 0; i < 4; i++) a[i] = As[kk][ty * 4 + i];
            #pragma unroll
            for (int j = 0; j < 4; j++) bv[j] = Bs[kk][tx * 4 + j];
            #pragma unroll
            for (int i = 0; i < 4; i++)
                #pragma unroll
                for (int j = 0; j < 4; j++)
                    acc[i][j] += a[i] * bv[j];
        }
        __syncthreads();
    }
    #pragma unroll
    for (int i = 0; i < 4; i++) {
        int s = m0 + ty * 4 + i;
        #pragma unroll
        for (int j = 0; j < 4; j++) {
            int n = tx * 4 + j;
            out[((size_t)(b_ * SS + s)) * DD + hh * DHH + n] = acc[i][j];
        }
    }
}

// ---------------- kernel 6: output projection + bias + residual --------------
__global__ void __launch_bounds__(256) gemm_out(const float* __restrict__ A,
                                                const float* __restrict__ W,
                                                const float* __restrict__ bias,
                                                const float* __restrict__ x,
                                                float* __restrict__ out) {
    __shared__ float As[16][128];
    __shared__ float Bs[16][128];
    int tid = threadIdx.x;
    int tx = tid & 15, ty = tid >> 4;
    int m0 = blockIdx.y * 128;
    int n0 = blockIdx.x * 128;
    float acc[8][8] = {};
    int arow = tid >> 2;
    int acol = (tid & 3) * 4;
    int brow = tid >> 5;
    int bcol = (tid & 31) * 4;
    for (int kt = 0; kt < 512; kt += 16) {
        #pragma unroll
        for (int i = 0; i < 2; i++) {
            int r = arow + i * 64;
            float4 v = *(const float4*)(A + (size_t)(m0 + r) * 512 + kt + acol);
            As[acol + 0][r] = v.x; As[acol + 1][r] = v.y;
            As[acol + 2][r] = v.z; As[acol + 3][r] = v.w;
        }
        #pragma unroll
        for (int i = 0; i < 2; i++) {
            int r = brow + i * 8;
            float4 v = *(const float4*)(W + (size_t)(kt + r) * 512 + n0 + bcol);
            *(float4*)&Bs[r][bcol] = v;
        }
        __syncthreads();
        #pragma unroll
        for (int kk = 0; kk < 16; kk++) {
            float a[8], bv[8];
            #pragma unroll
            for (int i = 0; i < 8; i++) a[i] = As[kk][ty * 8 + i];
            #pragma unroll
            for (int j = 0; j < 8; j++) bv[j] = Bs[kk][tx * 8 + j];
            #pragma unroll
            for (int i = 0; i < 8; i++)
                #pragma unroll
                for (int j = 0; j < 8; j++)
                    acc[i][j] += a[i] * bv[j];
        }
        __syncthreads();
    }
    #pragma unroll
    for (int i = 0; i < 8; i++) {
        int m = m0 + ty * 8 + i;
        #pragma unroll
        for (int j = 0; j < 8; j++) {
            int n = n0 + tx * 8 + j;
            out[(size_t)m * 512 + n] = acc[i][j] + bias[n] + x[(size_t)m * 512 + n];
        }
    }
}

// ---------------- host launcher ----------------------------------------------
extern "C" void kernel_launch(void* const* d_in, const int* in_sizes, int n_in,
                              void* d_out, int out_size) {
    const float* x    = (const float*)d_in[0];
    const int*   mask = (const int*)  d_in[1];
    const float* ln_g = (const float*)d_in[2];
    const float* ln_b = (const float*)d_in[3];
    const float* lna_g= (const float*)d_in[4];
    const float* lna_b= (const float*)d_in[5];
    const float* Wq   = (const float*)d_in[6];
    const float* bq   = (const float*)d_in[7];
    const float* Wk   = (const float*)d_in[8];
    const float* bk   = (const float*)d_in[9];
    const float* Wv   = (const float*)d_in[10];
    const float* bv   = (const float*)d_in[11];
    const float* Wd   = (const float*)d_in[12];
    const float* bd   = (const float*)d_in[13];
    float* out = (float*)d_out;

    float *h, *q, *k, *v, *scores, *ao;
    cudaGetSymbolAddress((void**)&h,      g_h);
    cudaGetSymbolAddress((void**)&q,      g_q);
    cudaGetSymbolAddress((void**)&k,      g_k);
    cudaGetSymbolAddress((void**)&v,      g_v);
    cudaGetSymbolAddress((void**)&scores, g_scores);
    cudaGetSymbolAddress((void**)&ao,     g_ao);

    // 1. pre-LN
    ln_kernel<<<BB * SS, 256>>>(x, ln_g, ln_b, h);
    // 2. QKV projections -> [B,H,S,DH]
    dim3 ggrid(4, 64);
    gemm_qkv<<<ggrid, 256>>>(h, Wq, bq, q);
    gemm_qkv<<<ggrid, 256>>>(h, Wk, bk, k);
    gemm_qkv<<<ggrid, 256>>>(h, Wv, bv, v);
    // 3. scores = Q K^T / 8
    dim3 sgrid(8, 8, BB * HH);
    scores_kernel<<<sgrid, 256>>>(q, k, scores);
    // 4. LN over key axis + mask + softmax (in place)
    lnsoftmax_kernel<<<BB * HH * SS, 256>>>(scores, mask, lna_g, lna_b);
    // 5. attn @ V -> [B,S,D]
    dim3 avgrid(8, BB * HH);
    av_kernel<<<avgrid, 256>>>(scores, v, ao);
    // 6. output projection + residual
    gemm_out<<<ggrid, 256>>>(ao, Wd, bd, x, out);
}

// round 10
// speedup vs baseline: 1.1786x; 1.1780x over previous
#include <cuda_runtime.h>
#include <cuda_bf16.h>
#include <cstdint>

#define EPSF 1e-5f

// ---------------- device scratch ---------------------------------------------
__device__ uint4 g_ha4[1048576];     // ha  [8192][1024] bf16 (hi 0..511 | lo 512..1023)
__device__ uint4 g_waug4[262144];    // wa  [4][512 n][1024] bf16 (W^T, hi k | lo k)
__device__ uint4 g_qaug4[1048576];   // qa  [128 bh][512 s][128] bf16 (hi 64 | lo 64), pre-scaled 1/8
__device__ uint4 g_kaug4[1048576];   // ka  same
__device__ uint4 g_vt4[1048576];     // vt  [128 bh][64 dh][1024] bf16 (hi t 0..511 | lo)
__device__ uint4 g_paug4[8388608];   // pa  [128 bh][512 s][1024] bf16 (hi 512 | lo 512) unnormalized exp
__device__ uint4 g_ao4[1048576];     // ao  [8192][1024] bf16 (hi | lo)
__device__ float g_rsinv[65536];     // 1/rowsum per (bh,s)
__device__ unsigned g_mb[131072];    // mask bits [8192 rows][16 words]

// ---------------- helpers -----------------------------------------------------
__device__ __forceinline__ uint32_t s2u(const void* p) {
    uint32_t a;
    asm("{ .reg .u64 t; cvta.to.shared.u64 t, %1; cvt.u32.u64 %0, t; }" : "=r"(a) : "l"(p));
    return a;
}
__device__ __forceinline__ void split2(float v, __nv_bfloat16& hi, __nv_bfloat16& lo) {
    hi = __float2bfloat16(v);
    lo = __float2bfloat16(v - __bfloat162float(hi));
}
__device__ __forceinline__ uint32_t pk(__nv_bfloat16 a, __nv_bfloat16 b) {
    return (uint32_t)__bfloat16_as_ushort(a) | ((uint32_t)__bfloat16_as_ushort(b) << 16);
}
__device__ __forceinline__ void ldm4(uint32_t* r, uint32_t a) {
    asm volatile("ldmatrix.sync.aligned.m8n8.x4.shared.b16 {%0,%1,%2,%3}, [%4];"
                 : "=r"(r[0]), "=r"(r[1]), "=r"(r[2]), "=r"(r[3]) : "r"(a));
}
__device__ __forceinline__ void mmabf(float* c, const uint32_t* a, const uint32_t* b) {
    asm volatile("mma.sync.aligned.m16n8k16.row.col.f32.bf16.bf16.f32 "
                 "{%0,%1,%2,%3},{%4,%5,%6,%7},{%8,%9},{%0,%1,%2,%3};"
                 : "+f"(c[0]), "+f"(c[1]), "+f"(c[2]), "+f"(c[3])
                 : "r"(a[0]), "r"(a[1]), "r"(a[2]), "r"(a[3]), "r"(b[0]), "r"(b[1]));
}

// copy a [rows x 64 bf16] plane from gmem into smem tile (stride 200 bf16) at colOff
__device__ __forceinline__ void ld_plane(const char* g, int rowStrideB, char* smBase,
                                         int colOff, int rows, int tid) {
    int total = rows * 8;
    for (int i = tid; i < total; i += 256) {
        int r = i >> 3, s = i & 7;
        uint4 v = *(const uint4*)(g + (size_t)r * rowStrideB + s * 16);
        *(uint4*)(smBase + (r * 200 + colOff + s * 8) * 2) = v;
    }
}

// ---------------- prep kernels ------------------------------------------------
__global__ void __launch_bounds__(256) prep_ln(const float* __restrict__ x,
                                               const float* __restrict__ g,
                                               const float* __restrict__ b,
                                               __nv_bfloat16* __restrict__ ha) {
    int row = blockIdx.x, t = threadIdx.x;
    const float* xr = x + (size_t)row * 512;
    float v0 = xr[t], v1 = xr[t + 256];
    __shared__ float s1[256], s2[256];
    s1[t] = v0 + v1; s2[t] = v0 * v0 + v1 * v1;
    __syncthreads();
    for (int o = 128; o > 0; o >>= 1) {
        if (t < o) { s1[t] += s1[t + o]; s2[t] += s2[t + o]; }
        __syncthreads();
    }
    float mu = s1[0] * (1.f / 512), inv = rsqrtf(s2[0] * (1.f / 512) - mu * mu + EPSF);
    __nv_bfloat16 hi, lo;
    size_t o = (size_t)row * 1024;
    split2((v0 - mu) * inv * g[t] + b[t], hi, lo);             ha[o + t] = hi;       ha[o + 512 + t] = lo;
    split2((v1 - mu) * inv * g[t + 256] + b[t + 256], hi, lo); ha[o + t + 256] = hi; ha[o + 768 + t] = lo;
}

__global__ void __launch_bounds__(256) prep_w(const float* __restrict__ W0, const float* __restrict__ W1,
                                              const float* __restrict__ W2, const float* __restrict__ W3,
                                              __nv_bfloat16* __restrict__ wa) {
    __shared__ float t[64][65];
    int w = blockIdx.z;
    const float* W = (w == 0) ? W0 : (w == 1) ? W1 : (w == 2) ? W2 : W3;
    int k0 = blockIdx.x * 64, n0 = blockIdx.y * 64;
    int tid = threadIdx.x;
    #pragma unroll
    for (int i = 0; i < 16; i++) {
        int idx = i * 256 + tid, r = idx >> 6, c = idx & 63;
        t[r][c] = W[(size_t)(k0 + r) * 512 + n0 + c];
    }
    __syncthreads();
    __nv_bfloat16* dst = wa + (size_t)w * 512 * 1024;
    #pragma unroll
    for (int i = 0; i < 16; i++) {
        int idx = i * 256 + tid, r = idx >> 6, c = idx & 63;
        float v = t[c][r];                   // = W[k0+c][n0+r]
        __nv_bfloat16 hi, lo; split2(v, hi, lo);
        dst[(size_t)(n0 + r) * 1024 + k0 + c]       = hi;
        dst[(size_t)(n0 + r) * 1024 + 512 + k0 + c] = lo;
    }
}

__global__ void __launch_bounds__(256) prep_mask(const int* __restrict__ mask, unsigned* __restrict__ mb) {
    int gid = blockIdx.x * 256 + threadIdx.x;          // 0..131071
    int r = gid >> 4, w = gid & 15;
    const int* p = mask + (size_t)r * 512 + w * 32;
    unsigned bits = 0;
    #pragma unroll
    for (int j = 0; j < 32; j++) bits |= (p[j] != 0 ? 1u : 0u) << j;
    mb[gid] = bits;
}

// ---------------- epilogue store for projections ------------------------------
__device__ __forceinline__ void proj_store(int mode, int m, int n, float v0, float v1,
                                           const float* bias, const float* x,
                                           __nv_bfloat16* obf, float* ofp) {
    v0 += __ldg(bias + n); v1 += __ldg(bias + n + 1);
    if (mode == 3) {
        size_t o = (size_t)m * 512 + n;
        float2 r; r.x = v0 + __ldg(x + o); r.y = v1 + __ldg(x + o + 1);
        *(float2*)(ofp + o) = r;
        return;
    }
    if (mode == 0) { v0 *= 0.125f; v1 *= 0.125f; }
    int bh = ((m >> 9) << 3) + (n >> 6), s = m & 511, dh = n & 63;
    __nv_bfloat16 h0, l0, h1, l1; split2(v0, h0, l0); split2(v1, h1, l1);
    if (mode == 2) {
        size_t base = ((size_t)bh * 64 + dh) * 1024 + s;
        obf[base] = h0; obf[base + 512] = l0;
        obf[base + 1024] = h1; obf[base + 1536] = l1;
    } else {
        size_t base = ((size_t)bh * 512 + s) * 128 + dh;
        *(uint32_t*)(obf + base)      = pk(h0, h1);
        *(uint32_t*)(obf + base + 64) = pk(l0, l1);
    }
}

// ---------------- projection GEMM: C[8192,512] = A @ W^T (+bias) --------------
__global__ void __launch_bounds__(256) gemm_proj(const __nv_bfloat16* __restrict__ A,
                                                 const __nv_bfloat16* __restrict__ Bw,
                                                 const float* __restrict__ bias, int mode,
                                                 __nv_bfloat16* __restrict__ obf,
                                                 float* __restrict__ ofp,
                                                 const float* __restrict__ x) {
    extern __shared__ char sm[];
    char* sA = sm;                 // [128][200] bf16
    char* sB = sm + 51200;         // [128][200] bf16
    uint32_t sAu = s2u(sA), sBu = s2u(sB);
    int tid = threadIdx.x, lane = tid & 31, warp = tid >> 5;
    int n0 = blockIdx.x * 128, m0 = blockIdx.y * 128;
    const char* Ab = (const char*)(A + (size_t)m0 * 1024);
    const char* Bb = (const char*)(Bw + (size_t)n0 * 1024);
    int wm = (warp >> 1) * 32, wn = (warp & 1) * 64;
    float c[2][8][4] = {};
    for (int ch = 0; ch < 8; ch++) {
        __syncthreads();
        // A aug = [hi | lo | hi]
        ld_plane(Ab + ch * 128, 2048, sA, 0, 128, tid);
        ld_plane(Ab + 1024 + ch * 128, 2048, sA, 64, 128, tid);
        ld_plane(Ab + ch * 128, 2048, sA, 128, 128, tid);
        // B aug = [hi | hi | lo]
        ld_plane(Bb + ch * 128, 2048, sB, 0, 128, tid);
        ld_plane(Bb + ch * 128, 2048, sB, 64, 128, tid);
        ld_plane(Bb + 1024 + ch * 128, 2048, sB, 128, 128, tid);
        __syncthreads();
        for (int ks = 0; ks < 12; ks++) {
            int k0 = ks * 16;
            uint32_t a[2][4];
            uint32_t aad = sAu + (uint32_t)(((wm + (lane & 15)) * 200 + k0 + ((lane >> 4) << 3)) * 2);
            ldm4(a[0], aad);
            ldm4(a[1], aad + 6400);
            #pragma unroll
            for (int np = 0; np < 4; np++) {
                uint32_t bad = sBu + (uint32_t)(((wn + np * 16 + (lane & 7) + ((lane >> 4) << 3)) * 200
                                                + k0 + (((lane >> 3) & 1) << 3)) * 2);
                uint32_t b4[4]; ldm4(b4, bad);
                mmabf(c[0][np * 2],     a[0], b4);
                mmabf(c[0][np * 2 + 1], a[0], b4 + 2);
                mmabf(c[1][np * 2],     a[1], b4);
                mmabf(c[1][np * 2 + 1], a[1], b4 + 2);
            }
        }
    }
    int g = lane >> 2, tg2 = (lane & 3) * 2;
    #pragma unroll
    for (int ms = 0; ms < 2; ms++)
        #pragma unroll
        for (int ns = 0; ns < 8; ns++) {
            int m = m0 + wm + ms * 16 + g;
            int n = n0 + wn + ns * 8 + tg2;
            proj_store(mode, m,     n, c[ms][ns][0], c[ms][ns][1], bias, x, obf, ofp);
            proj_store(mode, m + 8, n, c[ms][ns][2], c[ms][ns][3], bias, x, obf, ofp);
        }
}

// ---------------- scores: QK^T + LN + mask + softmax (fused) ------------------
__global__ void __launch_bounds__(256) gemm_scores(const __nv_bfloat16* __restrict__ Q,
                                                   const __nv_bfloat16* __restrict__ K,
                                                   const unsigned* __restrict__ mb,
                                                   const float* __restrict__ lg,
                                                   const float* __restrict__ lb,
                                                   __nv_bfloat16* __restrict__ pa,
                                                   float* __restrict__ rsinv) {
    extern __shared__ char sm[];
    float* sS = (float*)sm;                         // [64][512] fp32
    char* sQ = sm + 131072;                         // [64][200] bf16
    char* sK = sm + 131072 + 25600;                 // [128][200] bf16
    uint32_t sQu = s2u(sQ), sKu = s2u(sK);
    int tid = threadIdx.x, lane = tid & 31, warp = tid >> 5;
    int stile = blockIdx.x, bh = blockIdx.y;
    const char* Qb  = (const char*)(Q + ((size_t)bh * 512 + stile * 64) * 128);
    const char* Kb0 = (const char*)(K + (size_t)bh * 512 * 128);
    // Q aug = [hi | lo | hi]
    ld_plane(Qb, 256, sQ, 0, 64, tid);
    ld_plane(Qb + 128, 256, sQ, 64, 64, tid);
    ld_plane(Qb, 256, sQ, 128, 64, tid);
    int wm = (warp >> 2) * 32, wn = (warp & 3) * 32;
    int g = lane >> 2, tg2 = (lane & 3) * 2;
    for (int nt = 0; nt < 4; nt++) {
        __syncthreads();
        const char* Kb = Kb0 + (size_t)nt * 128 * 256;
        // K aug = [hi | hi | lo]
        ld_plane(Kb, 256, sK, 0, 128, tid);
        ld_plane(Kb, 256, sK, 64, 128, tid);
        ld_plane(Kb + 128, 256, sK, 128, 128, tid);
        __syncthreads();
        float c[2][4][4] = {};
        for (int ks = 0; ks < 12; ks++) {
            int k0 = ks * 16;
            uint32_t a[2][4];
            uint32_t aad = sQu + (uint32_t)(((wm + (lane & 15)) * 200 + k0 + ((lane >> 4) << 3)) * 2);
            ldm4(a[0], aad);
            ldm4(a[1], aad + 6400);
            #pragma unroll
            for (int np = 0; np < 2; np++) {
                uint32_t bad = sKu + (uint32_t)(((wn + np * 16 + (lane & 7) + ((lane >> 4) << 3)) * 200
                                                + k0 + (((lane >> 3) & 1) << 3)) * 2);
                uint32_t b4[4]; ldm4(b4, bad);
                mmabf(c[0][np * 2],     a[0], b4);
                mmabf(c[0][np * 2 + 1], a[0], b4 + 2);
                mmabf(c[1][np * 2],     a[1], b4);
                mmabf(c[1][np * 2 + 1], a[1], b4 + 2);
            }
        }
        #pragma unroll
        for (int ms = 0; ms < 2; ms++)
            #pragma unroll
            for (int ns = 0; ns < 4; ns++) {
                int r = wm + ms * 16 + g;
                int col = nt * 128 + wn + ns * 8 + tg2;
                *(float2*)&sS[r * 512 + col]       = make_float2(c[ms][ns][0], c[ms][ns][1]);
                *(float2*)&sS[(r + 8) * 512 + col] = make_float2(c[ms][ns][2], c[ms][ns][3]);
            }
    }
    __syncthreads();
    // ---- fused LN + mask + softmax: warp per row -----------------------------
    int b = bh >> 3;
    for (int rr = 0; rr < 8; rr++) {
        int r = warp * 8 + rr, qg = stile * 64 + r;
        float v[16];
        float4* rp = (float4*)(sS + r * 512 + lane * 16);
        float sum = 0.f, ssq = 0.f;
        #pragma unroll
        for (int j2 = 0; j2 < 4; j2++) {
            float4 t = rp[j2];
            v[j2 * 4] = t.x; v[j2 * 4 + 1] = t.y; v[j2 * 4 + 2] = t.z; v[j2 * 4 + 3] = t.w;
        }
        #pragma unroll
        for (int j = 0; j < 16; j++) { sum += v[j]; ssq += v[j] * v[j]; }
        #pragma unroll
        for (int o = 16; o > 0; o >>= 1) {
            sum += __shfl_xor_sync(0xFFFFFFFFu, sum, o);
            ssq += __shfl_xor_sync(0xFFFFFFFFu, ssq, o);
        }
        float mu = sum * (1.f / 512.f);
        float inv = rsqrtf(ssq * (1.f / 512.f) - mu * mu + EPSF);
        unsigned wbits = mb[((size_t)(b * 512 + qg)) * 16 + (lane >> 1)];
        unsigned bits = (wbits >> ((lane & 1) * 16)) & 0xFFFFu;
        float mx = -3.0e38f;
        #pragma unroll
        for (int j = 0; j < 16; j++) {
            int col = lane * 16 + j;
            v[j] = (v[j] - mu) * inv * __ldg(lg + col) + __ldg(lb + col);
            if ((bits >> j) & 1) mx = fmaxf(mx, v[j]);
        }
        #pragma unroll
        for (int o = 16; o > 0; o >>= 1) mx = fmaxf(mx, __shfl_xor_sync(0xFFFFFFFFu, mx, o));
        float den = 0.f;
        #pragma unroll
        for (int j = 0; j < 16; j++) {
            float p = ((bits >> j) & 1) ? __expf(v[j] - mx) : 0.f;
            v[j] = p; den += p;
        }
        #pragma unroll
        for (int o = 16; o > 0; o >>= 1) den += __shfl_xor_sync(0xFFFFFFFFu, den, o);
        if (lane == 0) rsinv[bh * 512 + qg] = 1.f / den;
        __nv_bfloat16* prow = pa + ((size_t)bh * 512 + qg) * 1024 + lane * 16;
        #pragma unroll
        for (int j = 0; j < 8; j++) {
            __nv_bfloat16 h0, l0, h1, l1;
            split2(v[2 * j], h0, l0); split2(v[2 * j + 1], h1, l1);
            ((uint32_t*)prow)[j]         = pk(h0, h1);
            ((uint32_t*)(prow + 512))[j] = pk(l0, l1);
        }
    }
}

// ---------------- AV: P_exp @ V, normalized in epilogue -----------------------
__global__ void __launch_bounds__(256) gemm_av(const __nv_bfloat16* __restrict__ P,
                                               const __nv_bfloat16* __restrict__ Vt,
                                               const float* __restrict__ rsinv,
                                               __nv_bfloat16* __restrict__ ao) {
    extern __shared__ char sm[];
    char* sA = sm;                 // [128][200]
    char* sB = sm + 51200;         // [64][200]
    uint32_t sAu = s2u(sA), sBu = s2u(sB);
    int tid = threadIdx.x, lane = tid & 31, warp = tid >> 5;
    int mt = blockIdx.x, bh = blockIdx.y;
    int m0 = mt * 128;
    const char* Ab = (const char*)(P + ((size_t)bh * 512 + m0) * 1024);
    const char* Bb = (const char*)(Vt + (size_t)bh * 64 * 1024);
    int wm = (warp >> 1) * 32, wn = (warp & 1) * 32;
    float c[2][4][4] = {};
    for (int ch = 0; ch < 8; ch++) {
        __syncthreads();
        // A = P aug [hi | lo | hi]
        ld_plane(Ab + ch * 128, 2048, sA, 0, 128, tid);
        ld_plane(Ab + 1024 + ch * 128, 2048, sA, 64, 128, tid);
        ld_plane(Ab + ch * 128, 2048, sA, 128, 128, tid);
        // B = V^T aug [hi | hi | lo]
        ld_plane(Bb + ch * 128, 2048, sB, 0, 64, tid);
        ld_plane(Bb + ch * 128, 2048, sB, 64, 64, tid);
        ld_plane(Bb + 1024 + ch * 128, 2048, sB, 128, 64, tid);
        __syncthreads();
        for (int ks = 0; ks < 12; ks++) {
            int k0 = ks * 16;
            uint32_t a[2][4];
            uint32_t aad = sAu + (uint32_t)(((wm + (lane & 15)) * 200 + k0 + ((lane >> 4) << 3)) * 2);
            ldm4(a[0], aad);
            ldm4(a[1], aad + 6400);
            #pragma unroll
            for (int np = 0; np < 2; np++) {
                uint32_t bad = sBu + (uint32_t)(((wn + np * 16 + (lane & 7) + ((lane >> 4) << 3)) * 200
                                                + k0 + (((lane >> 3) & 1) << 3)) * 2);
                uint32_t b4[4]; ldm4(b4, bad);
                mmabf(c[0][np * 2],     a[0], b4);
                mmabf(c[0][np * 2 + 1], a[0], b4 + 2);
                mmabf(c[1][np * 2],     a[1], b4);
                mmabf(c[1][np * 2 + 1], a[1], b4 + 2);
            }
        }
    }
    int b = bh >> 3, h = bh & 7;
    int g = lane >> 2, tg2 = (lane & 3) * 2;
    #pragma unroll
    for (int ms = 0; ms < 2; ms++)
        #pragma unroll
        for (int ns = 0; ns < 4; ns++) {
            int s0 = m0 + wm + ms * 16 + g;
            int dh = wn + ns * 8 + tg2;
            float r0 = __ldg(rsinv + bh * 512 + s0);
            float r1 = __ldg(rsinv + bh * 512 + s0 + 8);
            __nv_bfloat16 h0, l0, h1, l1;
            split2(c[ms][ns][0] * r0, h0, l0); split2(c[ms][ns][1] * r0, h1, l1);
            size_t base = ((size_t)(b * 512 + s0)) * 1024 + h * 64 + dh;
            *(uint32_t*)(ao + base)       = pk(h0, h1);
            *(uint32_t*)(ao + base + 512) = pk(l0, l1);
            split2(c[ms][ns][2] * r1, h0, l0); split2(c[ms][ns][3] * r1, h1, l1);
            size_t base2 = ((size_t)(b * 512 + s0 + 8)) * 1024 + h * 64 + dh;
            *(uint32_t*)(ao + base2)       = pk(h0, h1);
            *(uint32_t*)(ao + base2 + 512) = pk(l0, l1);
        }
}

// ---------------- host launcher ----------------------------------------------
extern "C" void kernel_launch(void* const* d_in, const int* in_sizes, int n_in,
                              void* d_out, int out_size) {
    const float* x    = (const float*)d_in[0];
    const int*   mask = (const int*)  d_in[1];
    const float* ln_g = (const float*)d_in[2];
    const float* ln_b = (const float*)d_in[3];
    const float* lna_g= (const float*)d_in[4];
    const float* lna_b= (const float*)d_in[5];
    const float* Wq   = (const float*)d_in[6];
    const float* bq   = (const float*)d_in[7];
    const float* Wk   = (const float*)d_in[8];
    const float* bk   = (const float*)d_in[9];
    const float* Wv   = (const float*)d_in[10];
    const float* bv   = (const float*)d_in[11];
    const float* Wd   = (const float*)d_in[12];
    const float* bd   = (const float*)d_in[13];
    float* out = (float*)d_out;

    __nv_bfloat16 *ha, *wa, *qa, *ka, *vt, *pa, *ao;
    float* rs; unsigned* mb;
    cudaGetSymbolAddress((void**)&ha, g_ha4);
    cudaGetSymbolAddress((void**)&wa, g_waug4);
    cudaGetSymbolAddress((void**)&qa, g_qaug4);
    cudaGetSymbolAddress((void**)&ka, g_kaug4);
    cudaGetSymbolAddress((void**)&vt, g_vt4);
    cudaGetSymbolAddress((void**)&pa, g_paug4);
    cudaGetSymbolAddress((void**)&ao, g_ao4);
    cudaGetSymbolAddress((void**)&rs, g_rsinv);
    cudaGetSymbolAddress((void**)&mb, g_mb);

    const int PROJ_SM = 102400;                    // 2 x [128][200] bf16
    const int SC_SM   = 131072 + 25600 + 51200;    // 207872
    const int AV_SM   = 51200 + 25600;             // 76800
    cudaFuncSetAttribute(gemm_proj,   cudaFuncAttributeMaxDynamicSharedMemorySize, PROJ_SM);
    cudaFuncSetAttribute(gemm_scores, cudaFuncAttributeMaxDynamicSharedMemorySize, SC_SM);
    cudaFuncSetAttribute(gemm_av,     cudaFuncAttributeMaxDynamicSharedMemorySize, AV_SM);

    prep_ln<<<8192, 256>>>(x, ln_g, ln_b, ha);
    prep_w<<<dim3(8, 8, 4), 256>>>(Wq, Wk, Wv, Wd, wa);
    prep_mask<<<512, 256>>>(mask, mb);

    dim3 pg(4, 64);
    gemm_proj<<<pg, 256, PROJ_SM>>>(ha, wa,                    bq, 0, qa, nullptr, nullptr);
    gemm_proj<<<pg, 256, PROJ_SM>>>(ha, wa + 1 * 512 * 1024,   bk, 1, ka, nullptr, nullptr);
    gemm_proj<<<pg, 256, PROJ_SM>>>(ha, wa + 2 * 512 * 1024,   bv, 2, vt, nullptr, nullptr);

    gemm_scores<<<dim3(8, 128), 256, SC_SM>>>(qa, ka, mb, lna_g, lna_b, pa, rs);
    gemm_av<<<dim3(4, 128), 256, AV_SM>>>(pa, vt, rs, ao);

    gemm_proj<<<pg, 256, PROJ_SM>>>(ao, wa + 3 * 512 * 1024,   bd, 3, nullptr, out, x);
}

// round 12
// speedup vs baseline: 1.7611x; 1.4943x over previous
#include <cuda_runtime.h>
#include <cuda_bf16.h>
#include <cstdint>

#define EPSF 1e-5f

// ---------------- device scratch ---------------------------------------------
__device__ uint4 g_ha4[1048576];     // ha  [8192][1024] bf16 (hi 0..511 | lo 512..1023)
__device__ uint4 g_waug4[262144];    // wa  [4][512 n][1024] bf16 (W^T, hi k | lo k)
__device__ uint4 g_qaug4[1048576];   // qa  [128 bh][512 s][128] bf16 (hi 64 | lo 64), pre-scaled 1/8
__device__ uint4 g_kaug4[1048576];   // ka  same
__device__ uint4 g_vt4[1048576];     // vt  [128 bh][64 dh][1024] bf16 (hi | lo)
__device__ uint4 g_paug4[8388608];   // pa  [128 bh][512 s][1024] bf16 (hi 512 | lo 512) unnormalized exp
__device__ uint4 g_ao4[1048576];     // ao  [8192][1024] bf16 (hi | lo)
__device__ float g_rsinv[65536];     // 1/rowsum per (bh,s)
__device__ unsigned g_mb[131072];    // mask bits [8192 rows][16 words]

// ---------------- helpers -----------------------------------------------------
__device__ __forceinline__ uint32_t s2u(const void* p) {
    uint32_t a;
    asm("{ .reg .u64 t; cvta.to.shared.u64 t, %1; cvt.u32.u64 %0, t; }" : "=r"(a) : "l"(p));
    return a;
}
__device__ __forceinline__ void split2(float v, __nv_bfloat16& hi, __nv_bfloat16& lo) {
    hi = __float2bfloat16(v);
    lo = __float2bfloat16(v - __bfloat162float(hi));
}
__device__ __forceinline__ uint32_t pk(__nv_bfloat16 a, __nv_bfloat16 b) {
    return (uint32_t)__bfloat16_as_ushort(a) | ((uint32_t)__bfloat16_as_ushort(b) << 16);
}
__device__ __forceinline__ void ldm4(uint32_t* r, uint32_t a) {
    asm volatile("ldmatrix.sync.aligned.m8n8.x4.shared.b16 {%0,%1,%2,%3}, [%4];"
                 : "=r"(r[0]), "=r"(r[1]), "=r"(r[2]), "=r"(r[3]) : "r"(a));
}
__device__ __forceinline__ void mmabf(float* c, const uint32_t* a, const uint32_t* b) {
    asm volatile("mma.sync.aligned.m16n8k16.row.col.f32.bf16.bf16.f32 "
                 "{%0,%1,%2,%3},{%4,%5,%6,%7},{%8,%9},{%0,%1,%2,%3};"
                 : "+f"(c[0]), "+f"(c[1]), "+f"(c[2]), "+f"(c[3])
                 : "r"(a[0]), "r"(a[1]), "r"(a[2]), "r"(a[3]), "r"(b[0]), "r"(b[1]));
}
__device__ __forceinline__ void cpa16(uint32_t sdst, const void* g) {
    asm volatile("cp.async.cg.shared.global [%0], [%1], 16;" :: "r"(sdst), "l"(g) : "memory");
}
#define CP_COMMIT() asm volatile("cp.async.commit_group;" ::: "memory")
#define CP_WAIT1()  asm volatile("cp.async.wait_group 1;" ::: "memory")
#define CP_WAIT0()  asm volatile("cp.async.wait_group 0;" ::: "memory")

// async-copy a [rows x (nseg*8) bf16] plane into smem tile (elem stride) at colOff
__device__ __forceinline__ void cp_plane(const char* g, int rowStrideB, uint32_t smU,
                                         int stride, int colOff, int rows, int nseg, int tid) {
    int total = rows * nseg;
    for (int i = tid; i < total; i += 256) {
        int r = i / nseg, s = i % nseg;
        cpa16(smU + (uint32_t)((r * stride + colOff + s * 8) * 2),
              g + (size_t)r * rowStrideB + s * 16);
    }
}

// ---------------- prep kernels ------------------------------------------------
__global__ void __launch_bounds__(256) prep_ln(const float* __restrict__ x,
                                               const float* __restrict__ g,
                                               const float* __restrict__ b,
                                               __nv_bfloat16* __restrict__ ha) {
    int row = blockIdx.x, t = threadIdx.x;
    const float* xr = x + (size_t)row * 512;
    float v0 = xr[t], v1 = xr[t + 256];
    __shared__ float s1[256], s2[256];
    s1[t] = v0 + v1; s2[t] = v0 * v0 + v1 * v1;
    __syncthreads();
    for (int o = 128; o > 0; o >>= 1) {
        if (t < o) { s1[t] += s1[t + o]; s2[t] += s2[t + o]; }
        __syncthreads();
    }
    float mu = s1[0] * (1.f / 512), inv = rsqrtf(s2[0] * (1.f / 512) - mu * mu + EPSF);
    __nv_bfloat16 hi, lo;
    size_t o = (size_t)row * 1024;
    split2((v0 - mu) * inv * g[t] + b[t], hi, lo);             ha[o + t] = hi;       ha[o + 512 + t] = lo;
    split2((v1 - mu) * inv * g[t + 256] + b[t + 256], hi, lo); ha[o + t + 256] = hi; ha[o + 768 + t] = lo;
}

__global__ void __launch_bounds__(256) prep_w(const float* __restrict__ W0, const float* __restrict__ W1,
                                              const float* __restrict__ W2, const float* __restrict__ W3,
                                              __nv_bfloat16* __restrict__ wa) {
    __shared__ float t[64][65];
    int w = blockIdx.z;
    const float* W = (w == 0) ? W0 : (w == 1) ? W1 : (w == 2) ? W2 : W3;
    int k0 = blockIdx.x * 64, n0 = blockIdx.y * 64;
    int tid = threadIdx.x;
    #pragma unroll
    for (int i = 0; i < 16; i++) {
        int idx = i * 256 + tid, r = idx >> 6, c = idx & 63;
        t[r][c] = W[(size_t)(k0 + r) * 512 + n0 + c];
    }
    __syncthreads();
    __nv_bfloat16* dst = wa + (size_t)w * 512 * 1024;
    #pragma unroll
    for (int i = 0; i < 16; i++) {
        int idx = i * 256 + tid, r = idx >> 6, c = idx & 63;
        float v = t[c][r];                   // = W[k0+c][n0+r]
        __nv_bfloat16 hi, lo; split2(v, hi, lo);
        dst[(size_t)(n0 + r) * 1024 + k0 + c]       = hi;
        dst[(size_t)(n0 + r) * 1024 + 512 + k0 + c] = lo;
    }
}

__global__ void __launch_bounds__(256) prep_mask(const int* __restrict__ mask, unsigned* __restrict__ mb) {
    int gid = blockIdx.x * 256 + threadIdx.x;          // 0..131071
    int r = gid >> 4, w = gid & 15;
    const int* p = mask + (size_t)r * 512 + w * 32;
    unsigned bits = 0;
    #pragma unroll
    for (int j = 0; j < 32; j++) bits |= (p[j] != 0 ? 1u : 0u) << j;
    mb[gid] = bits;
}

// ---------------- epilogue store for projections ------------------------------
__device__ __forceinline__ void proj_store(int mode, int m, int n, float v0, float v1,
                                           const float* bias, const float* x,
                                           __nv_bfloat16* obf, float* ofp) {
    v0 += __ldg(bias + n); v1 += __ldg(bias + n + 1);
    if (mode == 3) {
        size_t o = (size_t)m * 512 + n;
        float2 r; r.x = v0 + __ldg(x + o); r.y = v1 + __ldg(x + o + 1);
        *(float2*)(ofp + o) = r;
        return;
    }
    if (mode == 0) { v0 *= 0.125f; v1 *= 0.125f; }
    int bh = ((m >> 9) << 3) + (n >> 6), s = m & 511, dh = n & 63;
    __nv_bfloat16 h0, l0, h1, l1; split2(v0, h0, l0); split2(v1, h1, l1);
    if (mode == 2) {
        size_t base = ((size_t)bh * 64 + dh) * 1024 + s;
        obf[base] = h0; obf[base + 512] = l0;
        obf[base + 1024] = h1; obf[base + 1536] = l1;
    } else {
        size_t base = ((size_t)bh * 512 + s) * 128 + dh;
        *(uint32_t*)(obf + base)      = pk(h0, h1);
        *(uint32_t*)(obf + base + 64) = pk(l0, l1);
    }
}

// ---------------- projection GEMM: C[8192,512] = A @ W^T (+bias) --------------
// smem: double-buffered chunks of k=32 (planes hi|lo, stride 72): occ 2-3
__global__ void __launch_bounds__(256) gemm_proj(const __nv_bfloat16* __restrict__ A,
                                                 const __nv_bfloat16* __restrict__ Bw,
                                                 const float* __restrict__ bias, int mode,
                                                 __nv_bfloat16* __restrict__ obf,
                                                 float* __restrict__ ofp,
                                                 const float* __restrict__ x) {
    extern __shared__ char sm[];
    uint32_t smb = s2u(sm);
    // buf layout: A0 @0, B0 @18432, A1 @36864, B1 @55296  (each tile 128*72*2=18432)
    int tid = threadIdx.x, lane = tid & 31, warp = tid >> 5;
    int n0 = blockIdx.x * 128, m0 = blockIdx.y * 128;
    const char* Ab = (const char*)(A + (size_t)m0 * 1024);
    const char* Bb = (const char*)(Bw + (size_t)n0 * 1024);
    int wm = (warp >> 1) * 32, wn = (warp & 1) * 64;
    float c[2][8][4] = {};

    // preload chunk 0 (hi: bytes ch*64, lo: 1024 + ch*64; each plane 4 segs/row)
    cp_plane(Ab,        2048, smb,         72, 0,  128, 4, tid);
    cp_plane(Ab + 1024, 2048, smb,         72, 32, 128, 4, tid);
    cp_plane(Bb,        2048, smb + 18432, 72, 0,  128, 4, tid);
    cp_plane(Bb + 1024, 2048, smb + 18432, 72, 32, 128, 4, tid);
    CP_COMMIT();

    for (int ch = 0; ch < 16; ch++) {
        int cur = ch & 1;
        if (ch < 15) {
            uint32_t nb = smb + (cur ^ 1) * 36864;
            cp_plane(Ab + (ch + 1) * 64,        2048, nb,         72, 0,  128, 4, tid);
            cp_plane(Ab + 1024 + (ch + 1) * 64, 2048, nb,         72, 32, 128, 4, tid);
            cp_plane(Bb + (ch + 1) * 64,        2048, nb + 18432, 72, 0,  128, 4, tid);
            cp_plane(Bb + 1024 + (ch + 1) * 64, 2048, nb + 18432, 72, 32, 128, 4, tid);
            CP_COMMIT();
            CP_WAIT1();
        } else {
            CP_WAIT0();
        }
        __syncthreads();
        uint32_t sAu = smb + cur * 36864, sBu = sAu + 18432;
        #pragma unroll
        for (int p = 0; p < 3; p++) {
            int aOff = (p == 1) ? 32 : 0, bOff = (p == 2) ? 32 : 0;
            #pragma unroll
            for (int ks = 0; ks < 2; ks++) {
                int kA = aOff + ks * 16, kB = bOff + ks * 16;
                uint32_t a[2][4];
                uint32_t aad = sAu + (uint32_t)(((wm + (lane & 15)) * 72 + kA + ((lane >> 4) << 3)) * 2);
                ldm4(a[0], aad);
                ldm4(a[1], aad + 2304);          // +16 rows * 72 * 2
                #pragma unroll
                for (int np = 0; np < 4; np++) {
                    uint32_t bad = sBu + (uint32_t)(((wn + np * 16 + (lane & 7) + ((lane >> 4) << 3)) * 72
                                                    + kB + (((lane >> 3) & 1) << 3)) * 2);
                    uint32_t b4[4]; ldm4(b4, bad);
                    mmabf(c[0][np * 2],     a[0], b4);
                    mmabf(c[0][np * 2 + 1], a[0], b4 + 2);
                    mmabf(c[1][np * 2],     a[1], b4);
                    mmabf(c[1][np * 2 + 1], a[1], b4 + 2);
                }
            }
        }
        __syncthreads();
    }
    int g = lane >> 2, tg2 = (lane & 3) * 2;
    #pragma unroll
    for (int ms = 0; ms < 2; ms++)
        #pragma unroll
        for (int ns = 0; ns < 8; ns++) {
            int m = m0 + wm + ms * 16 + g;
            int n = n0 + wn + ns * 8 + tg2;
            proj_store(mode, m,     n, c[ms][ns][0], c[ms][ns][1], bias, x, obf, ofp);
            proj_store(mode, m + 8, n, c[ms][ns][2], c[ms][ns][3], bias, x, obf, ofp);
        }
}

// ---------------- scores: QK^T + LN + mask + softmax (fused) ------------------
__global__ void __launch_bounds__(256) gemm_scores(const __nv_bfloat16* __restrict__ Q,
                                                   const __nv_bfloat16* __restrict__ K,
                                                   const unsigned* __restrict__ mb,
                                                   const float* __restrict__ lg,
                                                   const float* __restrict__ lb,
                                                   __nv_bfloat16* __restrict__ pa,
                                                   float* __restrict__ rsinv) {
    extern __shared__ char sm[];
    float* sS = (float*)sm;                           // [64][512] fp32 = 131072
    uint32_t sQu = s2u(sm + 131072);                  // [64][136]  = 17408
    uint32_t sK0 = s2u(sm + 131072 + 17408);          // [128][136] = 34816 (x2)
    int tid = threadIdx.x, lane = tid & 31, warp = tid >> 5;
    int stile = blockIdx.x, bh = blockIdx.y;
    const char* Qb  = (const char*)(Q + ((size_t)bh * 512 + stile * 64) * 128);
    const char* Kb0 = (const char*)(K + (size_t)bh * 512 * 128);
    int wm = (warp >> 2) * 32, wn = (warp & 3) * 32;
    int g = lane >> 2, tg2 = (lane & 3) * 2;

    // group 0: Q (both planes) + K tile 0
    cp_plane(Qb,        256, sQu, 136, 0,  64, 8, tid);
    cp_plane(Qb + 128,  256, sQu, 136, 64, 64, 8, tid);
    cp_plane(Kb0,       256, sK0, 136, 0,  128, 8, tid);
    cp_plane(Kb0 + 128, 256, sK0, 136, 64, 128, 8, tid);
    CP_COMMIT();

    for (int nt = 0; nt < 4; nt++) {
        int cur = nt & 1;
        if (nt < 3) {
            const char* Kb = Kb0 + (size_t)(nt + 1) * 128 * 256;
            uint32_t nb = sK0 + (cur ^ 1) * 34816;
            cp_plane(Kb,       256, nb, 136, 0,  128, 8, tid);
            cp_plane(Kb + 128, 256, nb, 136, 64, 128, 8, tid);
            CP_COMMIT();
            CP_WAIT1();
        } else {
            CP_WAIT0();
        }
        __syncthreads();
        uint32_t sKu = sK0 + cur * 34816;
        float c[2][4][4] = {};
        #pragma unroll
        for (int p = 0; p < 3; p++) {
            int aOff = (p == 1) ? 64 : 0, bOff = (p == 2) ? 64 : 0;
            #pragma unroll
            for (int ks = 0; ks < 4; ks++) {
                int kA = aOff + ks * 16, kB = bOff + ks * 16;
                uint32_t a[2][4];
                uint32_t aad = sQu + (uint32_t)(((wm + (lane & 15)) * 136 + kA + ((lane >> 4) << 3)) * 2);
                ldm4(a[0], aad);
                ldm4(a[1], aad + 4352);          // +16 rows * 136 * 2
                #pragma unroll
                for (int np = 0; np < 2; np++) {
                    uint32_t bad = sKu + (uint32_t)(((wn + np * 16 + (lane & 7) + ((lane >> 4) << 3)) * 136
                                                    + kB + (((lane >> 3) & 1) << 3)) * 2);
                    uint32_t b4[4]; ldm4(b4, bad);
                    mmabf(c[0][np * 2],     a[0], b4);
                    mmabf(c[0][np * 2 + 1], a[0], b4 + 2);
                    mmabf(c[1][np * 2],     a[1], b4);
                    mmabf(c[1][np * 2 + 1], a[1], b4 + 2);
                }
            }
        }
        #pragma unroll
        for (int ms = 0; ms < 2; ms++)
            #pragma unroll
            for (int ns = 0; ns < 4; ns++) {
                int r = wm + ms * 16 + g;
                int col = nt * 128 + wn + ns * 8 + tg2;
                *(float2*)&sS[r * 512 + col]       = make_float2(c[ms][ns][0], c[ms][ns][1]);
                *(float2*)&sS[(r + 8) * 512 + col] = make_float2(c[ms][ns][2], c[ms][ns][3]);
            }
        __syncthreads();
    }
    // ---- fused LN + mask + softmax: warp per row -----------------------------
    int b = bh >> 3;
    for (int rr = 0; rr < 8; rr++) {
        int r = warp * 8 + rr, qg = stile * 64 + r;
        float v[16];
        float4* rp = (float4*)(sS + r * 512 + lane * 16);
        float sum = 0.f, ssq = 0.f;
        #pragma unroll
        for (int j2 = 0; j2 < 4; j2++) {
            float4 t = rp[j2];
            v[j2 * 4] = t.x; v[j2 * 4 + 1] = t.y; v[j2 * 4 + 2] = t.z; v[j2 * 4 + 3] = t.w;
        }
        #pragma unroll
        for (int j = 0; j < 16; j++) { sum += v[j]; ssq += v[j] * v[j]; }
        #pragma unroll
        for (int o = 16; o > 0; o >>= 1) {
            sum += __shfl_xor_sync(0xFFFFFFFFu, sum, o);
            ssq += __shfl_xor_sync(0xFFFFFFFFu, ssq, o);
        }
        float mu = sum * (1.f / 512.f);
        float inv = rsqrtf(ssq * (1.f / 512.f) - mu * mu + EPSF);
        unsigned wbits = mb[((size_t)(b * 512 + qg)) * 16 + (lane >> 1)];
        unsigned bits = (wbits >> ((lane & 1) * 16)) & 0xFFFFu;
        float mx = -3.0e38f;
        #pragma unroll
        for (int j = 0; j < 16; j++) {
            int col = lane * 16 + j;
            v[j] = (v[j] - mu) * inv * __ldg(lg + col) + __ldg(lb + col);
            if ((bits >> j) & 1) mx = fmaxf(mx, v[j]);
        }
        #pragma unroll
        for (int o = 16; o > 0; o >>= 1) mx = fmaxf(mx, __shfl_xor_sync(0xFFFFFFFFu, mx, o));
        float den = 0.f;
        #pragma unroll
        for (int j = 0; j < 16; j++) {
            float p = ((bits >> j) & 1) ? __expf(v[j] - mx) : 0.f;
            v[j] = p; den += p;
        }
        #pragma unroll
        for (int o = 16; o > 0; o >>= 1) den += __shfl_xor_sync(0xFFFFFFFFu, den, o);
        if (lane == 0) rsinv[bh * 512 + qg] = 1.f / den;
        __nv_bfloat16* prow = pa + ((size_t)bh * 512 + qg) * 1024 + lane * 16;
        #pragma unroll
        for (int j = 0; j < 8; j++) {
            __nv_bfloat16 h0, l0, h1, l1;
            split2(v[2 * j], h0, l0); split2(v[2 * j + 1], h1, l1);
            ((uint32_t*)prow)[j]         = pk(h0, h1);
            ((uint32_t*)(prow + 512))[j] = pk(l0, l1);
        }
    }
}

// ---------------- AV: P_exp @ V, normalized in epilogue -----------------------
__global__ void __launch_bounds__(256) gemm_av(const __nv_bfloat16* __restrict__ P,
                                               const __nv_bfloat16* __restrict__ Vt,
                                               const float* __restrict__ rsinv,
                                               __nv_bfloat16* __restrict__ ao) {
    extern __shared__ char sm[];
    uint32_t smb = s2u(sm);
    // layout: A0 @0 (34816), B0 @34816 (17408), A1 @52224, B1 @87040; total 104448
    int tid = threadIdx.x, lane = tid & 31, warp = tid >> 5;
    int mt = blockIdx.x, bh = blockIdx.y;
    int m0 = mt * 128;
    const char* Ab = (const char*)(P + ((size_t)bh * 512 + m0) * 1024);
    const char* Bb = (const char*)(Vt + (size_t)bh * 64 * 1024);
    int wm = (warp >> 1) * 32, wn = (warp & 1) * 32;
    float c[2][4][4] = {};

    cp_plane(Ab,        2048, smb,         136, 0,  128, 8, tid);
    cp_plane(Ab + 1024, 2048, smb,         136, 64, 128, 8, tid);
    cp_plane(Bb,        2048, smb + 34816, 136, 0,  64, 8, tid);
    cp_plane(Bb + 1024, 2048, smb + 34816, 136, 64, 64, 8, tid);
    CP_COMMIT();

    for (int ch = 0; ch < 8; ch++) {
        int cur = ch & 1;
        if (ch < 7) {
            uint32_t nb = smb + (cur ^ 1) * 52224;
            cp_plane(Ab + (ch + 1) * 128,        2048, nb,         136, 0,  128, 8, tid);
            cp_plane(Ab + 1024 + (ch + 1) * 128, 2048, nb,         136, 64, 128, 8, tid);
            cp_plane(Bb + (ch + 1) * 128,        2048, nb + 34816, 136, 0,  64, 8, tid);
            cp_plane(Bb + 1024 + (ch + 1) * 128, 2048, nb + 34816, 136, 64, 64, 8, tid);
            CP_COMMIT();
            CP_WAIT1();
        } else {
            CP_WAIT0();
        }
        __syncthreads();
        uint32_t sAu = smb + cur * 52224, sBu = sAu + 34816;
        #pragma unroll
        for (int p = 0; p < 3; p++) {
            int aOff = (p == 1) ? 64 : 0, bOff = (p == 2) ? 64 : 0;
            #pragma unroll
            for (int ks = 0; ks < 4; ks++) {
                int kA = aOff + ks * 16, kB = bOff + ks * 16;
                uint32_t a[2][4];
                uint32_t aad = sAu + (uint32_t)(((wm + (lane & 15)) * 136 + kA + ((lane >> 4) << 3)) * 2);
                ldm4(a[0], aad);
                ldm4(a[1], aad + 4352);
                #pragma unroll
                for (int np = 0; np < 2; np++) {
                    uint32_t bad = sBu + (uint32_t)(((wn + np * 16 + (lane & 7) + ((lane >> 4) << 3)) * 136
                                                    + kB + (((lane >> 3) & 1) << 3)) * 2);
                    uint32_t b4[4]; ldm4(b4, bad);
                    mmabf(c[0][np * 2],     a[0], b4);
                    mmabf(c[0][np * 2 + 1], a[0], b4 + 2);
                    mmabf(c[1][np * 2],     a[1], b4);
                    mmabf(c[1][np * 2 + 1], a[1], b4 + 2);
                }
            }
        }
        __syncthreads();
    }
    int b = bh >> 3, h = bh & 7;
    int g = lane >> 2, tg2 = (lane & 3) * 2;
    #pragma unroll
    for (int ms = 0; ms < 2; ms++)
        #pragma unroll
        for (int ns = 0; ns < 4; ns++) {
            int s0 = m0 + wm + ms * 16 + g;
            int dh = wn + ns * 8 + tg2;
            float r0 = __ldg(rsinv + bh * 512 + s0);
            float r1 = __ldg(rsinv + bh * 512 + s0 + 8);
            __nv_bfloat16 h0, l0, h1, l1;
            split2(c[ms][ns][0] * r0, h0, l0); split2(c[ms][ns][1] * r0, h1, l1);
            size_t base = ((size_t)(b * 512 + s0)) * 1024 + h * 64 + dh;
            *(uint32_t*)(ao + base)       = pk(h0, h1);
            *(uint32_t*)(ao + base + 512) = pk(l0, l1);
            split2(c[ms][ns][2] * r1, h0, l0); split2(c[ms][ns][3] * r1, h1, l1);
            size_t base2 = ((size_t)(b * 512 + s0 + 8)) * 1024 + h * 64 + dh;
            *(uint32_t*)(ao + base2)       = pk(h0, h1);
            *(uint32_t*)(ao + base2 + 512) = pk(l0, l1);
        }
}

// ---------------- host launcher ----------------------------------------------
extern "C" void kernel_launch(void* const* d_in, const int* in_sizes, int n_in,
                              void* d_out, int out_size) {
    const float* x    = (const float*)d_in[0];
    const int*   mask = (const int*)  d_in[1];
    const float* ln_g = (const float*)d_in[2];
    const float* ln_b = (const float*)d_in[3];
    const float* lna_g= (const float*)d_in[4];
    const float* lna_b= (const float*)d_in[5];
    const float* Wq   = (const float*)d_in[6];
    const float* bq   = (const float*)d_in[7];
    const float* Wk   = (const float*)d_in[8];
    const float* bk   = (const float*)d_in[9];
    const float* Wv   = (const float*)d_in[10];
    const float* bv   = (const float*)d_in[11];
    const float* Wd   = (const float*)d_in[12];
    const float* bd   = (const float*)d_in[13];
    float* out = (float*)d_out;

    __nv_bfloat16 *ha, *wa, *qa, *ka, *vt, *pa, *ao;
    float* rs; unsigned* mb;
    cudaGetSymbolAddress((void**)&ha, g_ha4);
    cudaGetSymbolAddress((void**)&wa, g_waug4);
    cudaGetSymbolAddress((void**)&qa, g_qaug4);
    cudaGetSymbolAddress((void**)&ka, g_kaug4);
    cudaGetSymbolAddress((void**)&vt, g_vt4);
    cudaGetSymbolAddress((void**)&pa, g_paug4);
    cudaGetSymbolAddress((void**)&ao, g_ao4);
    cudaGetSymbolAddress((void**)&rs, g_rsinv);
    cudaGetSymbolAddress((void**)&mb, g_mb);

    const int PROJ_SM = 73728;                     // 2 x (A 18432 + B 18432)
    const int SC_SM   = 131072 + 17408 + 2 * 34816; // 217920... = 218112
    const int AV_SM   = 2 * (34816 + 17408);       // 104448
    cudaFuncSetAttribute(gemm_proj,   cudaFuncAttributeMaxDynamicSharedMemorySize, PROJ_SM);
    cudaFuncSetAttribute(gemm_scores, cudaFuncAttributeMaxDynamicSharedMemorySize, 218112);
    cudaFuncSetAttribute(gemm_av,     cudaFuncAttributeMaxDynamicSharedMemorySize, AV_SM);

    prep_ln<<<8192, 256>>>(x, ln_g, ln_b, ha);
    prep_w<<<dim3(8, 8, 4), 256>>>(Wq, Wk, Wv, Wd, wa);
    prep_mask<<<512, 256>>>(mask, mb);

    dim3 pg(4, 64);
    gemm_proj<<<pg, 256, PROJ_SM>>>(ha, wa,                    bq, 0, qa, nullptr, nullptr);
    gemm_proj<<<pg, 256, PROJ_SM>>>(ha, wa + 1 * 512 * 1024,   bk, 1, ka, nullptr, nullptr);
    gemm_proj<<<pg, 256, PROJ_SM>>>(ha, wa + 2 * 512 * 1024,   bv, 2, vt, nullptr, nullptr);

    gemm_scores<<<dim3(8, 128), 256, 218112>>>(qa, ka, mb, lna_g, lna_b, pa, rs);
    gemm_av<<<dim3(4, 128), 256, AV_SM>>>(pa, vt, rs, ao);

    gemm_proj<<<pg, 256, PROJ_SM>>>(ao, wa + 3 * 512 * 1024,   bd, 3, nullptr, out, x);
}

// round 14
// speedup vs baseline: 1.8923x; 1.0745x over previous
#include <cuda_runtime.h>
#include <cuda_bf16.h>
#include <cstdint>

#define EPSF 1e-5f

// ---------------- device scratch ---------------------------------------------
__device__ uint4 g_ha4[1048576];     // ha  [8192][1024] bf16 (hi 0..511 | lo 512..1023)
__device__ uint4 g_waug4[262144];    // wa  [4][512 n][1024] bf16 (W^T, hi k | lo k)
__device__ uint4 g_qaug4[1048576];   // qa  [128 bh][512 s][128] bf16 (hi 64 | lo 64), pre-scaled 1/8
__device__ uint4 g_kaug4[1048576];   // ka  same
__device__ uint4 g_vt4[1048576];     // vt  [128 bh][64 dh][1024] bf16 (hi s | lo s)
__device__ uint4 g_ao4[1048576];     // ao  [8192][1024] bf16 (hi | lo)
__device__ unsigned g_mb[131072];    // mask bits [8192 rows][16 words]

// ---------------- helpers -----------------------------------------------------
__device__ __forceinline__ uint32_t s2u(const void* p) {
    uint32_t a;
    asm("{ .reg .u64 t; cvta.to.shared.u64 t, %1; cvt.u32.u64 %0, t; }" : "=r"(a) : "l"(p));
    return a;
}
__device__ __forceinline__ void split2(float v, __nv_bfloat16& hi, __nv_bfloat16& lo) {
    hi = __float2bfloat16(v);
    lo = __float2bfloat16(v - __bfloat162float(hi));
}
__device__ __forceinline__ uint32_t pk(__nv_bfloat16 a, __nv_bfloat16 b) {
    return (uint32_t)__bfloat16_as_ushort(a) | ((uint32_t)__bfloat16_as_ushort(b) << 16);
}
__device__ __forceinline__ void ldm4(uint32_t* r, uint32_t a) {
    asm volatile("ldmatrix.sync.aligned.m8n8.x4.shared.b16 {%0,%1,%2,%3}, [%4];"
                 : "=r"(r[0]), "=r"(r[1]), "=r"(r[2]), "=r"(r[3]) : "r"(a));
}
__device__ __forceinline__ void mmabf(float* c, const uint32_t* a, const uint32_t* b) {
    asm volatile("mma.sync.aligned.m16n8k16.row.col.f32.bf16.bf16.f32 "
                 "{%0,%1,%2,%3},{%4,%5,%6,%7},{%8,%9},{%0,%1,%2,%3};"
                 : "+f"(c[0]), "+f"(c[1]), "+f"(c[2]), "+f"(c[3])
                 : "r"(a[0]), "r"(a[1]), "r"(a[2]), "r"(a[3]), "r"(b[0]), "r"(b[1]));
}
__device__ __forceinline__ void cpa16(uint32_t sdst, const void* g) {
    asm volatile("cp.async.cg.shared.global [%0], [%1], 16;" :: "r"(sdst), "l"(g) : "memory");
}
#define CP_COMMIT() asm volatile("cp.async.commit_group;" ::: "memory")
#define CP_WAIT1()  asm volatile("cp.async.wait_group 1;" ::: "memory")
#define CP_WAIT0()  asm volatile("cp.async.wait_group 0;" ::: "memory")

// async-copy a [rows x (nseg*8) bf16] plane into smem tile (elem stride) at colOff
__device__ __forceinline__ void cp_plane(const char* g, int rowStrideB, uint32_t smU,
                                         int stride, int colOff, int rows, int nseg, int tid) {
    int total = rows * nseg;
    for (int i = tid; i < total; i += 256) {
        int r = i / nseg, s = i % nseg;
        cpa16(smU + (uint32_t)((r * stride + colOff + s * 8) * 2),
              g + (size_t)r * rowStrideB + s * 16);
    }
}

// ---------------- prep kernels ------------------------------------------------
__global__ void __launch_bounds__(256) prep_ln(const float* __restrict__ x,
                                               const float* __restrict__ g,
                                               const float* __restrict__ b,
                                               __nv_bfloat16* __restrict__ ha) {
    int row = blockIdx.x, t = threadIdx.x;
    const float* xr = x + (size_t)row * 512;
    float v0 = xr[t], v1 = xr[t + 256];
    __shared__ float s1[256], s2[256];
    s1[t] = v0 + v1; s2[t] = v0 * v0 + v1 * v1;
    __syncthreads();
    for (int o = 128; o > 0; o >>= 1) {
        if (t < o) { s1[t] += s1[t + o]; s2[t] += s2[t + o]; }
        __syncthreads();
    }
    float mu = s1[0] * (1.f / 512), inv = rsqrtf(s2[0] * (1.f / 512) - mu * mu + EPSF);
    __nv_bfloat16 hi, lo;
    size_t o = (size_t)row * 1024;
    split2((v0 - mu) * inv * g[t] + b[t], hi, lo);             ha[o + t] = hi;       ha[o + 512 + t] = lo;
    split2((v1 - mu) * inv * g[t + 256] + b[t + 256], hi, lo); ha[o + t + 256] = hi; ha[o + 768 + t] = lo;
}

__global__ void __launch_bounds__(256) prep_w(const float* __restrict__ W0, const float* __restrict__ W1,
                                              const float* __restrict__ W2, const float* __restrict__ W3,
                                              __nv_bfloat16* __restrict__ wa) {
    __shared__ float t[64][65];
    int w = blockIdx.z;
    const float* W = (w == 0) ? W0 : (w == 1) ? W1 : (w == 2) ? W2 : W3;
    int k0 = blockIdx.x * 64, n0 = blockIdx.y * 64;
    int tid = threadIdx.x;
    #pragma unroll
    for (int i = 0; i < 16; i++) {
        int idx = i * 256 + tid, r = idx >> 6, c = idx & 63;
        t[r][c] = W[(size_t)(k0 + r) * 512 + n0 + c];
    }
    __syncthreads();
    __nv_bfloat16* dst = wa + (size_t)w * 512 * 1024;
    #pragma unroll
    for (int i = 0; i < 16; i++) {
        int idx = i * 256 + tid, r = idx >> 6, c = idx & 63;
        float v = t[c][r];                   // = W[k0+c][n0+r]
        __nv_bfloat16 hi, lo; split2(v, hi, lo);
        dst[(size_t)(n0 + r) * 1024 + k0 + c]       = hi;
        dst[(size_t)(n0 + r) * 1024 + 512 + k0 + c] = lo;
    }
}

__global__ void __launch_bounds__(256) prep_mask(const int* __restrict__ mask, unsigned* __restrict__ mb) {
    int gid = blockIdx.x * 256 + threadIdx.x;          // 0..131071
    int r = gid >> 4, w = gid & 15;
    const int* p = mask + (size_t)r * 512 + w * 32;
    unsigned bits = 0;
    #pragma unroll
    for (int j = 0; j < 32; j++) bits |= (p[j] != 0 ? 1u : 0u) << j;
    mb[gid] = bits;
}

// ---------------- epilogue store for projections ------------------------------
__device__ __forceinline__ void proj_store(int mode, int m, int n, float v0, float v1,
                                           const float* bias, const float* x,
                                           __nv_bfloat16* obf, float* ofp) {
    v0 += __ldg(bias + n); v1 += __ldg(bias + n + 1);
    if (mode == 3) {
        size_t o = (size_t)m * 512 + n;
        float2 r; r.x = v0 + __ldg(x + o); r.y = v1 + __ldg(x + o + 1);
        *(float2*)(ofp + o) = r;
        return;
    }
    if (mode == 0) { v0 *= 0.125f; v1 *= 0.125f; }
    int bh = ((m >> 9) << 3) + (n >> 6), s = m & 511, dh = n & 63;
    __nv_bfloat16 h0, l0, h1, l1; split2(v0, h0, l0); split2(v1, h1, l1);
    if (mode == 2) {
        size_t base = ((size_t)bh * 64 + dh) * 1024 + s;
        obf[base] = h0; obf[base + 512] = l0;
        obf[base + 1024] = h1; obf[base + 1536] = l1;
    } else {
        size_t base = ((size_t)bh * 512 + s) * 128 + dh;
        *(uint32_t*)(obf + base)      = pk(h0, h1);
        *(uint32_t*)(obf + base + 64) = pk(l0, l1);
    }
}

// ---------------- shared GEMM body (k=32 double-buffered chunks) --------------
__device__ __forceinline__ void proj_body(const __nv_bfloat16* A, const __nv_bfloat16* Bw,
                                          const float* bias, int mode,
                                          __nv_bfloat16* obf, float* ofp, const float* x,
                                          int n0, int m0, char* sm) {
    uint32_t smb = s2u(sm);
    int tid = threadIdx.x, lane = tid & 31, warp = tid >> 5;
    const char* Ab = (const char*)(A + (size_t)m0 * 1024);
    const char* Bb = (const char*)(Bw + (size_t)n0 * 1024);
    int wm = (warp >> 1) * 32, wn = (warp & 1) * 64;
    float c[2][8][4] = {};

    cp_plane(Ab,        2048, smb,         72, 0,  128, 4, tid);
    cp_plane(Ab + 1024, 2048, smb,         72, 32, 128, 4, tid);
    cp_plane(Bb,        2048, smb + 18432, 72, 0,  128, 4, tid);
    cp_plane(Bb + 1024, 2048, smb + 18432, 72, 32, 128, 4, tid);
    CP_COMMIT();

    for (int ch = 0; ch < 16; ch++) {
        int cur = ch & 1;
        if (ch < 15) {
            uint32_t nb = smb + (cur ^ 1) * 36864;
            cp_plane(Ab + (ch + 1) * 64,        2048, nb,         72, 0,  128, 4, tid);
            cp_plane(Ab + 1024 + (ch + 1) * 64, 2048, nb,         72, 32, 128, 4, tid);
            cp_plane(Bb + (ch + 1) * 64,        2048, nb + 18432, 72, 0,  128, 4, tid);
            cp_plane(Bb + 1024 + (ch + 1) * 64, 2048, nb + 18432, 72, 32, 128, 4, tid);
            CP_COMMIT();
            CP_WAIT1();
        } else {
            CP_WAIT0();
        }
        __syncthreads();
        uint32_t sAu = smb + cur * 36864, sBu = sAu + 18432;
        #pragma unroll
        for (int p = 0; p < 3; p++) {
            int aOff = (p == 1) ? 32 : 0, bOff = (p == 2) ? 32 : 0;
            #pragma unroll
            for (int ks = 0; ks < 2; ks++) {
                int kA = aOff + ks * 16, kB = bOff + ks * 16;
                uint32_t a[2][4];
                uint32_t aad = sAu + (uint32_t)(((wm + (lane & 15)) * 72 + kA + ((lane >> 4) << 3)) * 2);
                ldm4(a[0], aad);
                ldm4(a[1], aad + 2304);
                #pragma unroll
                for (int np = 0; np < 4; np++) {
                    uint32_t bad = sBu + (uint32_t)(((wn + np * 16 + (lane & 7) + ((lane >> 4) << 3)) * 72
                                                    + kB + (((lane >> 3) & 1) << 3)) * 2);
                    uint32_t b4[4]; ldm4(b4, bad);
                    mmabf(c[0][np * 2],     a[0], b4);
                    mmabf(c[0][np * 2 + 1], a[0], b4 + 2);
                    mmabf(c[1][np * 2],     a[1], b4);
                    mmabf(c[1][np * 2 + 1], a[1], b4 + 2);
                }
            }
        }
        __syncthreads();
    }
    int g = lane >> 2, tg2 = (lane & 3) * 2;
    #pragma unroll
    for (int ms = 0; ms < 2; ms++)
        #pragma unroll
        for (int ns = 0; ns < 8; ns++) {
            int m = m0 + wm + ms * 16 + g;
            int n = n0 + wn + ns * 8 + tg2;
            proj_store(mode, m,     n, c[ms][ns][0], c[ms][ns][1], bias, x, obf, ofp);
            proj_store(mode, m + 8, n, c[ms][ns][2], c[ms][ns][3], bias, x, obf, ofp);
        }
}

// fused Q/K/V projection: blockIdx.z selects which
__global__ void __launch_bounds__(256) gemm_qkv3(const __nv_bfloat16* __restrict__ A,
                                                 const __nv_bfloat16* __restrict__ wa,
                                                 const float* __restrict__ bq,
                                                 const float* __restrict__ bk,
                                                 const float* __restrict__ bv,
                                                 __nv_bfloat16* __restrict__ qa,
                                                 __nv_bfloat16* __restrict__ ka,
                                                 __nv_bfloat16* __restrict__ vt) {
    extern __shared__ char sm[];
    int z = blockIdx.z;
    const __nv_bfloat16* Bw = wa + (size_t)z * 512 * 1024;
    const float* bias = (z == 0) ? bq : (z == 1) ? bk : bv;
    __nv_bfloat16* obf = (z == 0) ? qa : (z == 1) ? ka : vt;
    proj_body(A, Bw, bias, z, obf, nullptr, nullptr, blockIdx.x * 128, blockIdx.y * 128, sm);
}

// output projection + residual
__global__ void __launch_bounds__(256) gemm_out(const __nv_bfloat16* __restrict__ A,
                                                const __nv_bfloat16* __restrict__ Bw,
                                                const float* __restrict__ bias,
                                                const float* __restrict__ x,
                                                float* __restrict__ out) {
    extern __shared__ char sm[];
    proj_body(A, Bw, bias, 3, nullptr, out, x, blockIdx.x * 128, blockIdx.y * 128, sm);
}

// ---------------- fused attention: QK^T + LN + mask + softmax + P@V ----------
// smem layout:
//   sS/P  @0       : 131072  (fp32 scores [64][512]; then P split-bf16, stride 2048B, XOR-swizzled)
//   sQ    @131072  : 17408   ([64][136] bf16, hi@0 lo@64)
//   sKV0  @148480  : 34816   (K: [128][136]; V: [64][272], hi@0 lo@136)
//   sKV1  @183296  : 34816
//   sRs   @218112  : 256     (64 floats: 1/rowsum)
__global__ void __launch_bounds__(256) gemm_attn(const __nv_bfloat16* __restrict__ Q,
                                                 const __nv_bfloat16* __restrict__ K,
                                                 const __nv_bfloat16* __restrict__ Vt,
                                                 const unsigned* __restrict__ mb,
                                                 const float* __restrict__ lg,
                                                 const float* __restrict__ lb,
                                                 __nv_bfloat16* __restrict__ ao) {
    extern __shared__ char sm[];
    float* sS = (float*)sm;
    uint32_t sSu = s2u(sm);
    uint32_t sQu = sSu + 131072;
    uint32_t sKV0 = sSu + 148480;
    float* sRs = (float*)(sm + 218112);
    int tid = threadIdx.x, lane = tid & 31, warp = tid >> 5;
    int stile = blockIdx.x, bh = blockIdx.y;
    const char* Qb  = (const char*)(Q + ((size_t)bh * 512 + stile * 64) * 128);
    const char* Kb0 = (const char*)(K + (size_t)bh * 512 * 128);
    const char* Vb  = (const char*)(Vt + (size_t)bh * 64 * 1024);
    int g = lane >> 2, tg2 = (lane & 3) * 2;

    // ---------------- phase 1: scores = Q K^T ---------------------------------
    {
        int wm = (warp >> 2) * 32, wn = (warp & 3) * 32;
        cp_plane(Qb,        256, sQu, 136, 0,  64, 8, tid);
        cp_plane(Qb + 128,  256, sQu, 136, 64, 64, 8, tid);
        cp_plane(Kb0,       256, sKV0, 136, 0,  128, 8, tid);
        cp_plane(Kb0 + 128, 256, sKV0, 136, 64, 128, 8, tid);
        CP_COMMIT();
        for (int nt = 0; nt < 4; nt++) {
            int cur = nt & 1;
            if (nt < 3) {
                const char* Kb = Kb0 + (size_t)(nt + 1) * 128 * 256;
                uint32_t nb = sKV0 + (cur ^ 1) * 34816;
                cp_plane(Kb,       256, nb, 136, 0,  128, 8, tid);
                cp_plane(Kb + 128, 256, nb, 136, 64, 128, 8, tid);
                CP_COMMIT();
                CP_WAIT1();
            } else {
                CP_WAIT0();
            }
            __syncthreads();
            uint32_t sKu = sKV0 + cur * 34816;
            float c[2][4][4] = {};
            #pragma unroll
            for (int p = 0; p < 3; p++) {
                int aOff = (p == 1) ? 64 : 0, bOff = (p == 2) ? 64 : 0;
                #pragma unroll
                for (int ks = 0; ks < 4; ks++) {
                    int kA = aOff + ks * 16, kB = bOff + ks * 16;
                    uint32_t a[2][4];
                    uint32_t aad = sQu + (uint32_t)(((wm + (lane & 15)) * 136 + kA + ((lane >> 4) << 3)) * 2);
                    ldm4(a[0], aad);
                    ldm4(a[1], aad + 4352);
                    #pragma unroll
                    for (int np = 0; np < 2; np++) {
                        uint32_t bad = sKu + (uint32_t)(((wn + np * 16 + (lane & 7) + ((lane >> 4) << 3)) * 136
                                                        + kB + (((lane >> 3) & 1) << 3)) * 2);
                        uint32_t b4[4]; ldm4(b4, bad);
                        mmabf(c[0][np * 2],     a[0], b4);
                        mmabf(c[0][np * 2 + 1], a[0], b4 + 2);
                        mmabf(c[1][np * 2],     a[1], b4);
                        mmabf(c[1][np * 2 + 1], a[1], b4 + 2);
                    }
                }
            }
            #pragma unroll
            for (int ms = 0; ms < 2; ms++)
                #pragma unroll
                for (int ns = 0; ns < 4; ns++) {
                    int r = wm + ms * 16 + g;
                    int col = nt * 128 + wn + ns * 8 + tg2;
                    *(float2*)&sS[r * 512 + col]       = make_float2(c[ms][ns][0], c[ms][ns][1]);
                    *(float2*)&sS[(r + 8) * 512 + col] = make_float2(c[ms][ns][2], c[ms][ns][3]);
                }
            __syncthreads();
        }
    }

    // prefetch V chunk 0 (overlaps softmax)
    cp_plane(Vb,        2048, sKV0, 272, 0,   64, 16, tid);
    cp_plane(Vb + 1024, 2048, sKV0, 272, 136, 64, 16, tid);
    CP_COMMIT();

    // ---------------- phase 2: LN + mask + softmax, P in place (swizzled) -----
    {
        int b = bh >> 3;
        for (int rr = 0; rr < 8; rr++) {
            int r = warp * 8 + rr, qg = stile * 64 + r;
            float v[16];
            float4* rp = (float4*)(sS + r * 512 + lane * 16);
            float sum = 0.f, ssq = 0.f;
            #pragma unroll
            for (int j2 = 0; j2 < 4; j2++) {
                float4 t = rp[j2];
                v[j2 * 4] = t.x; v[j2 * 4 + 1] = t.y; v[j2 * 4 + 2] = t.z; v[j2 * 4 + 3] = t.w;
            }
            #pragma unroll
            for (int j = 0; j < 16; j++) { sum += v[j]; ssq += v[j] * v[j]; }
            #pragma unroll
            for (int o = 16; o > 0; o >>= 1) {
                sum += __shfl_xor_sync(0xFFFFFFFFu, sum, o);
                ssq += __shfl_xor_sync(0xFFFFFFFFu, ssq, o);
            }
            float mu = sum * (1.f / 512.f);
            float inv = rsqrtf(ssq * (1.f / 512.f) - mu * mu + EPSF);
            unsigned wbits = mb[((size_t)(b * 512 + qg)) * 16 + (lane >> 1)];
            unsigned bits = (wbits >> ((lane & 1) * 16)) & 0xFFFFu;
            float mx = -3.0e38f;
            #pragma unroll
            for (int j = 0; j < 16; j++) {
                int col = lane * 16 + j;
                v[j] = (v[j] - mu) * inv * __ldg(lg + col) + __ldg(lb + col);
                if ((bits >> j) & 1) mx = fmaxf(mx, v[j]);
            }
            #pragma unroll
            for (int o = 16; o > 0; o >>= 1) mx = fmaxf(mx, __shfl_xor_sync(0xFFFFFFFFu, mx, o));
            float den = 0.f;
            #pragma unroll
            for (int j = 0; j < 16; j++) {
                float p = ((bits >> j) & 1) ? __expf(v[j] - mx) : 0.f;
                v[j] = p; den += p;
            }
            #pragma unroll
            for (int o = 16; o > 0; o >>= 1) den += __shfl_xor_sync(0xFFFFFFFFu, den, o);
            if (lane == 0) sRs[r] = 1.f / den;
            // split + swizzled in-place store (row r fully read above)
            uint32_t h[8], l[8];
            #pragma unroll
            for (int j = 0; j < 8; j++) {
                __nv_bfloat16 h0, l0, h1, l1;
                split2(v[2 * j], h0, l0); split2(v[2 * j + 1], h1, l1);
                h[j] = pk(h0, h1); l[j] = pk(l0, l1);
            }
            int r7 = r & 7;
            char* rowp = sm + r * 2048;
            uint32_t s0 = (uint32_t)(((lane * 2) ^ r7) << 4);
            uint32_t s1 = (uint32_t)(((lane * 2 + 1) ^ r7) << 4);
            *(uint4*)(rowp + s0)        = make_uint4(h[0], h[1], h[2], h[3]);
            *(uint4*)(rowp + s1)        = make_uint4(h[4], h[5], h[6], h[7]);
            *(uint4*)(rowp + 1024 + s0) = make_uint4(l[0], l[1], l[2], l[3]);
            *(uint4*)(rowp + 1024 + s1) = make_uint4(l[4], l[5], l[6], l[7]);
        }
    }

    // ---------------- phase 3: out = P @ V^T (normalized) ---------------------
    {
        int wm2 = (warp >> 2) * 32, wn2 = (warp & 3) * 16;
        float c2[2][2][4] = {};
        for (int ch = 0; ch < 4; ch++) {
            int cur = ch & 1;
            if (ch < 3) {
                uint32_t nb = sKV0 + (cur ^ 1) * 34816;
                cp_plane(Vb + (ch + 1) * 256,        2048, nb, 272, 0,   64, 16, tid);
                cp_plane(Vb + 1024 + (ch + 1) * 256, 2048, nb, 272, 136, 64, 16, tid);
                CP_COMMIT();
                CP_WAIT1();
            } else {
                CP_WAIT0();
            }
            __syncthreads();
            uint32_t sVu = sKV0 + cur * 34816;
            #pragma unroll
            for (int p = 0; p < 3; p++) {
                int aPl = (p == 1) ? 64 : 0;          // P: [hi, lo, hi]
                int bOff = (p == 2) ? 136 : 0;        // V: [hi, hi, lo]
                #pragma unroll
                for (int ks = 0; ks < 8; ks++) {
                    uint32_t a[2][4];
                    int seg = aPl + ch * 16 + ks * 2 + (lane >> 4);
                    int rA = wm2 + (lane & 15);
                    ldm4(a[0], sSu + (uint32_t)(rA * 2048) + (uint32_t)(((seg ^ (rA & 7))) << 4));
                    int rA2 = rA + 16;
                    ldm4(a[1], sSu + (uint32_t)(rA2 * 2048) + (uint32_t)(((seg ^ (rA2 & 7))) << 4));
                    uint32_t bad = sVu + (uint32_t)(((wn2 + (lane & 7) + ((lane >> 4) << 3)) * 272
                                                    + bOff + ks * 16 + (((lane >> 3) & 1) << 3)) * 2);
                    uint32_t b4[4]; ldm4(b4, bad);
                    mmabf(c2[0][0], a[0], b4);
                    mmabf(c2[0][1], a[0], b4 + 2);
                    mmabf(c2[1][0], a[1], b4);
                    mmabf(c2[1][1], a[1], b4 + 2);
                }
            }
            __syncthreads();
        }
        int b = bh >> 3, h = bh & 7;
        #pragma unroll
        for (int ms = 0; ms < 2; ms++)
            #pragma unroll
            for (int nf = 0; nf < 2; nf++) {
                int rloc = wm2 + ms * 16 + g;
                int s0g = stile * 64 + rloc;
                int dh = wn2 + nf * 8 + tg2;
                float r0 = sRs[rloc], r1 = sRs[rloc + 8];
                __nv_bfloat16 h0, l0, h1, l1;
                split2(c2[ms][nf][0] * r0, h0, l0); split2(c2[ms][nf][1] * r0, h1, l1);
                size_t base = ((size_t)(b * 512 + s0g)) * 1024 + h * 64 + dh;
                *(uint32_t*)(ao + base)       = pk(h0, h1);
                *(uint32_t*)(ao + base + 512) = pk(l0, l1);
                split2(c2[ms][nf][2] * r1, h0, l0); split2(c2[ms][nf][3] * r1, h1, l1);
                size_t base2 = ((size_t)(b * 512 + s0g + 8)) * 1024 + h * 64 + dh;
                *(uint32_t*)(ao + base2)       = pk(h0, h1);
                *(uint32_t*)(ao + base2 + 512) = pk(l0, l1);
            }
    }
}

// ---------------- host launcher ----------------------------------------------
extern "C" void kernel_launch(void* const* d_in, const int* in_sizes, int n_in,
                              void* d_out, int out_size) {
    const float* x    = (const float*)d_in[0];
    const int*   mask = (const int*)  d_in[1];
    const float* ln_g = (const float*)d_in[2];
    const float* ln_b = (const float*)d_in[3];
    const float* lna_g= (const float*)d_in[4];
    const float* lna_b= (const float*)d_in[5];
    const float* Wq   = (const float*)d_in[6];
    const float* bq   = (const float*)d_in[7];
    const float* Wk   = (const float*)d_in[8];
    const float* bk   = (const float*)d_in[9];
    const float* Wv   = (const float*)d_in[10];
    const float* bv   = (const float*)d_in[11];
    const float* Wd   = (const float*)d_in[12];
    const float* bd   = (const float*)d_in[13];
    float* out = (float*)d_out;

    __nv_bfloat16 *ha, *wa, *qa, *ka, *vt, *ao;
    unsigned* mb;
    cudaGetSymbolAddress((void**)&ha, g_ha4);
    cudaGetSymbolAddress((void**)&wa, g_waug4);
    cudaGetSymbolAddress((void**)&qa, g_qaug4);
    cudaGetSymbolAddress((void**)&ka, g_kaug4);
    cudaGetSymbolAddress((void**)&vt, g_vt4);
    cudaGetSymbolAddress((void**)&ao, g_ao4);
    cudaGetSymbolAddress((void**)&mb, g_mb);

    const int PROJ_SM = 73728;
    const int ATTN_SM = 218368;
    cudaFuncSetAttribute(gemm_qkv3, cudaFuncAttributeMaxDynamicSharedMemorySize, PROJ_SM);
    cudaFuncSetAttribute(gemm_out,  cudaFuncAttributeMaxDynamicSharedMemorySize, PROJ_SM);
    cudaFuncSetAttribute(gemm_attn, cudaFuncAttributeMaxDynamicSharedMemorySize, ATTN_SM);

    prep_ln<<<8192, 256>>>(x, ln_g, ln_b, ha);
    prep_w<<<dim3(8, 8, 4), 256>>>(Wq, Wk, Wv, Wd, wa);
    prep_mask<<<512, 256>>>(mask, mb);

    gemm_qkv3<<<dim3(4, 64, 3), 256, PROJ_SM>>>(ha, wa, bq, bk, bv, qa, ka, vt);
    gemm_attn<<<dim3(8, 128), 256, ATTN_SM>>>(qa, ka, vt, mb, lna_g, lna_b, ao);
    gemm_out<<<dim3(4, 64), 256, PROJ_SM>>>(ao, wa + 3 * 512 * 1024, bd, x, out);
}

// round 16
// speedup vs baseline: 2.4560x; 1.2979x over previous
#include <cuda_runtime.h>
#include <cuda_bf16.h>
#include <cstdint>

#define EPSF 1e-5f

// ---------------- device scratch ---------------------------------------------
__device__ uint4 g_ha4[1048576];     // ha  [8192][1024] bf16 (hi 0..511 | lo 512..1023)
__device__ uint4 g_waug4[262144];    // wa  [4][512 n][1024] bf16 (W^T, hi k | lo k)
__device__ uint4 g_qaug4[1048576];   // qa  [128 bh][512 s][128] bf16 (hi 64 | lo 64), pre-scaled 1/8
__device__ uint4 g_kaug4[1048576];   // ka  same
__device__ uint4 g_vt4[1048576];     // vt  [128 bh][64 dh][1024] bf16 (hi s | lo s)
__device__ uint4 g_ao4[1048576];     // ao  [8192][1024] bf16 (hi | lo)
__device__ unsigned g_mb[131072];    // mask bits [8192 rows][16 words]

// ---------------- helpers -----------------------------------------------------
__device__ __forceinline__ uint32_t s2u(const void* p) {
    uint32_t a;
    asm("{ .reg .u64 t; cvta.to.shared.u64 t, %1; cvt.u32.u64 %0, t; }" : "=r"(a) : "l"(p));
    return a;
}
__device__ __forceinline__ void split2(float v, __nv_bfloat16& hi, __nv_bfloat16& lo) {
    hi = __float2bfloat16(v);
    lo = __float2bfloat16(v - __bfloat162float(hi));
}
__device__ __forceinline__ uint32_t pk(__nv_bfloat16 a, __nv_bfloat16 b) {
    return (uint32_t)__bfloat16_as_ushort(a) | ((uint32_t)__bfloat16_as_ushort(b) << 16);
}
__device__ __forceinline__ void ldm4(uint32_t* r, uint32_t a) {
    asm volatile("ldmatrix.sync.aligned.m8n8.x4.shared.b16 {%0,%1,%2,%3}, [%4];"
                 : "=r"(r[0]), "=r"(r[1]), "=r"(r[2]), "=r"(r[3]) : "r"(a));
}
__device__ __forceinline__ void mmabf(float* c, const uint32_t* a, const uint32_t* b) {
    asm volatile("mma.sync.aligned.m16n8k16.row.col.f32.bf16.bf16.f32 "
                 "{%0,%1,%2,%3},{%4,%5,%6,%7},{%8,%9},{%0,%1,%2,%3};"
                 : "+f"(c[0]), "+f"(c[1]), "+f"(c[2]), "+f"(c[3])
                 : "r"(a[0]), "r"(a[1]), "r"(a[2]), "r"(a[3]), "r"(b[0]), "r"(b[1]));
}
__device__ __forceinline__ void cpa16(uint32_t sdst, const void* g) {
    asm volatile("cp.async.cg.shared.global [%0], [%1], 16;" :: "r"(sdst), "l"(g) : "memory");
}
#define CP_COMMIT() asm volatile("cp.async.commit_group;" ::: "memory")
#define CP_WAIT2()  asm volatile("cp.async.wait_group 2;" ::: "memory")
#define CP_WAIT1()  asm volatile("cp.async.wait_group 1;" ::: "memory")
#define CP_WAIT0()  asm volatile("cp.async.wait_group 0;" ::: "memory")

// async-copy a [rows x (nseg*8) bf16] plane into smem tile (elem stride) at colOff
__device__ __forceinline__ void cp_plane(const char* g, int rowStrideB, uint32_t smU,
                                         int stride, int colOff, int rows, int nseg, int tid) {
    int total = rows * nseg;
    for (int i = tid; i < total; i += 256) {
        int r = i / nseg, s = i % nseg;
        cpa16(smU + (uint32_t)((r * stride + colOff + s * 8) * 2),
              g + (size_t)r * rowStrideB + s * 16);
    }
}

// ---------------- prep kernels ------------------------------------------------
__global__ void __launch_bounds__(256) prep_ln(const float* __restrict__ x,
                                               const float* __restrict__ g,
                                               const float* __restrict__ b,
                                               __nv_bfloat16* __restrict__ ha) {
    int row = blockIdx.x, t = threadIdx.x;
    const float* xr = x + (size_t)row * 512;
    float v0 = xr[t], v1 = xr[t + 256];
    __shared__ float s1[256], s2[256];
    s1[t] = v0 + v1; s2[t] = v0 * v0 + v1 * v1;
    __syncthreads();
    for (int o = 128; o > 0; o >>= 1) {
        if (t < o) { s1[t] += s1[t + o]; s2[t] += s2[t + o]; }
        __syncthreads();
    }
    float mu = s1[0] * (1.f / 512), inv = rsqrtf(s2[0] * (1.f / 512) - mu * mu + EPSF);
    __nv_bfloat16 hi, lo;
    size_t o = (size_t)row * 1024;
    split2((v0 - mu) * inv * g[t] + b[t], hi, lo);             ha[o + t] = hi;       ha[o + 512 + t] = lo;
    split2((v1 - mu) * inv * g[t + 256] + b[t + 256], hi, lo); ha[o + t + 256] = hi; ha[o + 768 + t] = lo;
}

__global__ void __launch_bounds__(256) prep_w(const float* __restrict__ W0, const float* __restrict__ W1,
                                              const float* __restrict__ W2, const float* __restrict__ W3,
                                              __nv_bfloat16* __restrict__ wa) {
    __shared__ float t[64][65];
    int w = blockIdx.z;
    const float* W = (w == 0) ? W0 : (w == 1) ? W1 : (w == 2) ? W2 : W3;
    int k0 = blockIdx.x * 64, n0 = blockIdx.y * 64;
    int tid = threadIdx.x;
    #pragma unroll
    for (int i = 0; i < 16; i++) {
        int idx = i * 256 + tid, r = idx >> 6, c = idx & 63;
        t[r][c] = W[(size_t)(k0 + r) * 512 + n0 + c];
    }
    __syncthreads();
    __nv_bfloat16* dst = wa + (size_t)w * 512 * 1024;
    #pragma unroll
    for (int i = 0; i < 16; i++) {
        int idx = i * 256 + tid, r = idx >> 6, c = idx & 63;
        float v = t[c][r];                   // = W[k0+c][n0+r]
        __nv_bfloat16 hi, lo; split2(v, hi, lo);
        dst[(size_t)(n0 + r) * 1024 + k0 + c]       = hi;
        dst[(size_t)(n0 + r) * 1024 + 512 + k0 + c] = lo;
    }
}

__global__ void __launch_bounds__(256) prep_mask(const int* __restrict__ mask, unsigned* __restrict__ mb) {
    int gid = blockIdx.x * 256 + threadIdx.x;          // 0..131071
    int r = gid >> 4, w = gid & 15;
    const int* p = mask + (size_t)r * 512 + w * 32;
    unsigned bits = 0;
    #pragma unroll
    for (int j = 0; j < 32; j++) bits |= (p[j] != 0 ? 1u : 0u) << j;
    mb[gid] = bits;
}

// ---------------- epilogue store for projections ------------------------------
__device__ __forceinline__ void proj_store(int mode, int m, int n, float v0, float v1,
                                           const float* bias, const float* x,
                                           __nv_bfloat16* obf, float* ofp) {
    v0 += __ldg(bias + n); v1 += __ldg(bias + n + 1);
    if (mode == 3) {
        size_t o = (size_t)m * 512 + n;
        float2 r; r.x = v0 + __ldg(x + o); r.y = v1 + __ldg(x + o + 1);
        *(float2*)(ofp + o) = r;
        return;
    }
    if (mode == 0) { v0 *= 0.125f; v1 *= 0.125f; }
    int bh = ((m >> 9) << 3) + (n >> 6), s = m & 511, dh = n & 63;
    __nv_bfloat16 h0, l0, h1, l1; split2(v0, h0, l0); split2(v1, h1, l1);
    if (mode == 2) {
        size_t base = ((size_t)bh * 64 + dh) * 1024 + s;
        obf[base] = h0; obf[base + 512] = l0;
        obf[base + 1024] = h1; obf[base + 1536] = l1;
    } else {
        size_t base = ((size_t)bh * 512 + s) * 128 + dh;
        *(uint32_t*)(obf + base)      = pk(h0, h1);
        *(uint32_t*)(obf + base + 64) = pk(l0, l1);
    }
}

// ---------------- shared GEMM body (k=32 chunks, 3-stage pipeline) ------------
__device__ __forceinline__ void proj_chunk_load(const char* Ab, const char* Bb,
                                                uint32_t buf, int ch, int tid) {
    cp_plane(Ab + ch * 64,        2048, buf,         72, 0,  128, 4, tid);
    cp_plane(Ab + 1024 + ch * 64, 2048, buf,         72, 32, 128, 4, tid);
    cp_plane(Bb + ch * 64,        2048, buf + 18432, 72, 0,  128, 4, tid);
    cp_plane(Bb + 1024 + ch * 64, 2048, buf + 18432, 72, 32, 128, 4, tid);
}

__device__ __forceinline__ void proj_body(const __nv_bfloat16* A, const __nv_bfloat16* Bw,
                                          const float* bias, int mode,
                                          __nv_bfloat16* obf, float* ofp, const float* x,
                                          int n0, int m0, char* sm) {
    uint32_t smb = s2u(sm);
    int tid = threadIdx.x, lane = tid & 31, warp = tid >> 5;
    const char* Ab = (const char*)(A + (size_t)m0 * 1024);
    const char* Bb = (const char*)(Bw + (size_t)n0 * 1024);
    int wm = (warp >> 1) * 32, wn = (warp & 1) * 64;
    float c[2][8][4] = {};

    proj_chunk_load(Ab, Bb, smb, 0, tid);             CP_COMMIT();
    proj_chunk_load(Ab, Bb, smb + 36864, 1, tid);     CP_COMMIT();

    for (int ch = 0; ch < 16; ch++) {
        if (ch + 2 < 16) {
            proj_chunk_load(Ab, Bb, smb + ((ch + 2) % 3) * 36864, ch + 2, tid);
            CP_COMMIT();
        }
        if (ch < 14)      CP_WAIT2();
        else if (ch == 14) CP_WAIT1();
        else               CP_WAIT0();
        __syncthreads();
        uint32_t sAu = smb + (ch % 3) * 36864, sBu = sAu + 18432;
        #pragma unroll
        for (int p = 0; p < 3; p++) {
            int aOff = (p == 1) ? 32 : 0, bOff = (p == 2) ? 32 : 0;
            #pragma unroll
            for (int ks = 0; ks < 2; ks++) {
                int kA = aOff + ks * 16, kB = bOff + ks * 16;
                uint32_t a[2][4];
                uint32_t aad = sAu + (uint32_t)(((wm + (lane & 15)) * 72 + kA + ((lane >> 4) << 3)) * 2);
                ldm4(a[0], aad);
                ldm4(a[1], aad + 2304);
                #pragma unroll
                for (int np = 0; np < 4; np++) {
                    uint32_t bad = sBu + (uint32_t)(((wn + np * 16 + (lane & 7) + ((lane >> 4) << 3)) * 72
                                                    + kB + (((lane >> 3) & 1) << 3)) * 2);
                    uint32_t b4[4]; ldm4(b4, bad);
                    mmabf(c[0][np * 2],     a[0], b4);
                    mmabf(c[0][np * 2 + 1], a[0], b4 + 2);
                    mmabf(c[1][np * 2],     a[1], b4);
                    mmabf(c[1][np * 2 + 1], a[1], b4 + 2);
                }
            }
        }
        __syncthreads();
    }
    int g = lane >> 2, tg2 = (lane & 3) * 2;
    #pragma unroll
    for (int ms = 0; ms < 2; ms++)
        #pragma unroll
        for (int ns = 0; ns < 8; ns++) {
            int m = m0 + wm + ms * 16 + g;
            int n = n0 + wn + ns * 8 + tg2;
            proj_store(mode, m,     n, c[ms][ns][0], c[ms][ns][1], bias, x, obf, ofp);
            proj_store(mode, m + 8, n, c[ms][ns][2], c[ms][ns][3], bias, x, obf, ofp);
        }
}

// fused Q/K/V projection: blockIdx.z selects which
__global__ void __launch_bounds__(256, 2) gemm_qkv3(const __nv_bfloat16* __restrict__ A,
                                                    const __nv_bfloat16* __restrict__ wa,
                                                    const float* __restrict__ bq,
                                                    const float* __restrict__ bk,
                                                    const float* __restrict__ bv,
                                                    __nv_bfloat16* __restrict__ qa,
                                                    __nv_bfloat16* __restrict__ ka,
                                                    __nv_bfloat16* __restrict__ vt) {
    extern __shared__ char sm[];
    int z = blockIdx.z;
    const __nv_bfloat16* Bw = wa + (size_t)z * 512 * 1024;
    const float* bias = (z == 0) ? bq : (z == 1) ? bk : bv;
    __nv_bfloat16* obf = (z == 0) ? qa : (z == 1) ? ka : vt;
    proj_body(A, Bw, bias, z, obf, nullptr, nullptr, blockIdx.x * 128, blockIdx.y * 128, sm);
}

// output projection + residual
__global__ void __launch_bounds__(256, 2) gemm_out(const __nv_bfloat16* __restrict__ A,
                                                   const __nv_bfloat16* __restrict__ Bw,
                                                   const float* __restrict__ bias,
                                                   const float* __restrict__ x,
                                                   float* __restrict__ out) {
    extern __shared__ char sm[];
    proj_body(A, Bw, bias, 3, nullptr, out, x, blockIdx.x * 128, blockIdx.y * 128, sm);
}

// ---------------- fused attention: QK^T + LN + mask + softmax + P@V ----------
// smem layout:
//   sS/P  @0       : 131072  (fp32 scores [64][512]; then P split-bf16, stride 2048B, XOR-swizzled)
//   sQ    @131072  : 17408   ([64][136] bf16, hi@0 lo@64; lg/lb staged here for phase 2)
//   sKV0  @148480  : 34816   (K: [128][136]; V: [64][272], hi@0 lo@136)
//   sKV1  @183296  : 34816
//   sRs   @218112  : 256     (64 floats: 1/rowsum)
__global__ void __launch_bounds__(256) gemm_attn(const __nv_bfloat16* __restrict__ Q,
                                                 const __nv_bfloat16* __restrict__ K,
                                                 const __nv_bfloat16* __restrict__ Vt,
                                                 const unsigned* __restrict__ mb,
                                                 const float* __restrict__ lg,
                                                 const float* __restrict__ lb,
                                                 __nv_bfloat16* __restrict__ ao) {
    extern __shared__ char sm[];
    float* sS = (float*)sm;
    uint32_t sSu = s2u(sm);
    uint32_t sQu = sSu + 131072;
    uint32_t sKV0 = sSu + 148480;
    float* sRs = (float*)(sm + 218112);
    int tid = threadIdx.x, lane = tid & 31, warp = tid >> 5;
    int stile = blockIdx.x, bh = blockIdx.y;
    const char* Qb  = (const char*)(Q + ((size_t)bh * 512 + stile * 64) * 128);
    const char* Kb0 = (const char*)(K + (size_t)bh * 512 * 128);
    const char* Vb  = (const char*)(Vt + (size_t)bh * 64 * 1024);
    int g = lane >> 2, tg2 = (lane & 3) * 2;

    // ---------------- phase 1: scores = Q K^T ---------------------------------
    {
        int wm = (warp >> 2) * 32, wn = (warp & 3) * 32;
        cp_plane(Qb,        256, sQu, 136, 0,  64, 8, tid);
        cp_plane(Qb + 128,  256, sQu, 136, 64, 64, 8, tid);
        cp_plane(Kb0,       256, sKV0, 136, 0,  128, 8, tid);
        cp_plane(Kb0 + 128, 256, sKV0, 136, 64, 128, 8, tid);
        CP_COMMIT();
        for (int nt = 0; nt < 4; nt++) {
            int cur = nt & 1;
            if (nt < 3) {
                const char* Kb = Kb0 + (size_t)(nt + 1) * 128 * 256;
                uint32_t nb = sKV0 + (cur ^ 1) * 34816;
                cp_plane(Kb,       256, nb, 136, 0,  128, 8, tid);
                cp_plane(Kb + 128, 256, nb, 136, 64, 128, 8, tid);
                CP_COMMIT();
                CP_WAIT1();
            } else {
                CP_WAIT0();
            }
            __syncthreads();
            uint32_t sKu = sKV0 + cur * 34816;
            float c[2][4][4] = {};
            #pragma unroll
            for (int p = 0; p < 3; p++) {
                int aOff = (p == 1) ? 64 : 0, bOff = (p == 2) ? 64 : 0;
                #pragma unroll
                for (int ks = 0; ks < 4; ks++) {
                    int kA = aOff + ks * 16, kB = bOff + ks * 16;
                    uint32_t a[2][4];
                    uint32_t aad = sQu + (uint32_t)(((wm + (lane & 15)) * 136 + kA + ((lane >> 4) << 3)) * 2);
                    ldm4(a[0], aad);
                    ldm4(a[1], aad + 4352);
                    #pragma unroll
                    for (int np = 0; np < 2; np++) {
                        uint32_t bad = sKu + (uint32_t)(((wn + np * 16 + (lane & 7) + ((lane >> 4) << 3)) * 136
                                                        + kB + (((lane >> 3) & 1) << 3)) * 2);
                        uint32_t b4[4]; ldm4(b4, bad);
                        mmabf(c[0][np * 2],     a[0], b4);
                        mmabf(c[0][np * 2 + 1], a[0], b4 + 2);
                        mmabf(c[1][np * 2],     a[1], b4);
                        mmabf(c[1][np * 2 + 1], a[1], b4 + 2);
                    }
                }
            }
            #pragma unroll
            for (int ms = 0; ms < 2; ms++)
                #pragma unroll
                for (int ns = 0; ns < 4; ns++) {
                    int r = wm + ms * 16 + g;
                    int col = nt * 128 + wn + ns * 8 + tg2;
                    *(float2*)&sS[r * 512 + col]       = make_float2(c[ms][ns][0], c[ms][ns][1]);
                    *(float2*)&sS[(r + 8) * 512 + col] = make_float2(c[ms][ns][2], c[ms][ns][3]);
                }
            __syncthreads();
        }
    }

    // prefetch V chunk 0 (overlaps softmax); stage lg/lb into sQ area
    cp_plane(Vb,        2048, sKV0, 272, 0,   64, 16, tid);
    cp_plane(Vb + 1024, 2048, sKV0, 272, 136, 64, 16, tid);
    CP_COMMIT();
    float* slg = (float*)(sm + 131072);
    float* slb = slg + 512;
    for (int i = tid; i < 512; i += 256) { slg[i] = __ldg(lg + i); slb[i] = __ldg(lb + i); }
    __syncthreads();

    // ---------------- phase 2: LN + mask + softmax, P in place (swizzled) -----
    {
        int b = bh >> 3;
        for (int rr = 0; rr < 8; rr++) {
            int r = warp * 8 + rr, qg = stile * 64 + r;
            float v[16];
            float4* rp = (float4*)(sS + r * 512 + lane * 16);
            float sum = 0.f, ssq = 0.f;
            #pragma unroll
            for (int j2 = 0; j2 < 4; j2++) {
                float4 t = rp[j2];
                v[j2 * 4] = t.x; v[j2 * 4 + 1] = t.y; v[j2 * 4 + 2] = t.z; v[j2 * 4 + 3] = t.w;
            }
            #pragma unroll
            for (int j = 0; j < 16; j++) { sum += v[j]; ssq += v[j] * v[j]; }
            #pragma unroll
            for (int o = 16; o > 0; o >>= 1) {
                sum += __shfl_xor_sync(0xFFFFFFFFu, sum, o);
                ssq += __shfl_xor_sync(0xFFFFFFFFu, ssq, o);
            }
            float mu = sum * (1.f / 512.f);
            float inv = rsqrtf(ssq * (1.f / 512.f) - mu * mu + EPSF);
            unsigned wbits = mb[((size_t)(b * 512 + qg)) * 16 + (lane >> 1)];
            unsigned bits = (wbits >> ((lane & 1) * 16)) & 0xFFFFu;
            float mx = -3.0e38f;
            #pragma unroll
            for (int j = 0; j < 16; j++) {
                int col = lane * 16 + j;
                v[j] = (v[j] - mu) * inv * slg[col] + slb[col];
                if ((bits >> j) & 1) mx = fmaxf(mx, v[j]);
            }
            #pragma unroll
            for (int o = 16; o > 0; o >>= 1) mx = fmaxf(mx, __shfl_xor_sync(0xFFFFFFFFu, mx, o));
            float den = 0.f;
            #pragma unroll
            for (int j = 0; j < 16; j++) {
                float p = ((bits >> j) & 1) ? __expf(v[j] - mx) : 0.f;
                v[j] = p; den += p;
            }
            #pragma unroll
            for (int o = 16; o > 0; o >>= 1) den += __shfl_xor_sync(0xFFFFFFFFu, den, o);
            if (lane == 0) sRs[r] = 1.f / den;
            // split + swizzled in-place store (row r fully read above)
            uint32_t h[8], l[8];
            #pragma unroll
            for (int j = 0; j < 8; j++) {
                __nv_bfloat16 h0, l0, h1, l1;
                split2(v[2 * j], h0, l0); split2(v[2 * j + 1], h1, l1);
                h[j] = pk(h0, h1); l[j] = pk(l0, l1);
            }
            int r7 = r & 7;
            char* rowp = sm + r * 2048;
            uint32_t s0 = (uint32_t)(((lane * 2) ^ r7) << 4);
            uint32_t s1 = (uint32_t)(((lane * 2 + 1) ^ r7) << 4);
            *(uint4*)(rowp + s0)        = make_uint4(h[0], h[1], h[2], h[3]);
            *(uint4*)(rowp + s1)        = make_uint4(h[4], h[5], h[6], h[7]);
            *(uint4*)(rowp + 1024 + s0) = make_uint4(l[0], l[1], l[2], l[3]);
            *(uint4*)(rowp + 1024 + s1) = make_uint4(l[4], l[5], l[6], l[7]);
        }
    }

    // ---------------- phase 3: out = P @ V^T (normalized) ---------------------
    {
        int wm2 = (warp >> 2) * 32, wn2 = (warp & 3) * 16;
        float c2[2][2][4] = {};
        for (int ch = 0; ch < 4; ch++) {
            int cur = ch & 1;
            if (ch < 3) {
                uint32_t nb = sKV0 + (cur ^ 1) * 34816;
                cp_plane(Vb + (ch + 1) * 256,        2048, nb, 272, 0,   64, 16, tid);
                cp_plane(Vb + 1024 + (ch + 1) * 256, 2048, nb, 272, 136, 64, 16, tid);
                CP_COMMIT();
                CP_WAIT1();
            } else {
                CP_WAIT0();
            }
            __syncthreads();
            uint32_t sVu = sKV0 + cur * 34816;
            #pragma unroll
            for (int p = 0; p < 3; p++) {
                int aPl = (p == 1) ? 64 : 0;          // P: [hi, lo, hi]
                int bOff = (p == 2) ? 136 : 0;        // V: [hi, hi, lo]
                #pragma unroll
                for (int ks = 0; ks < 8; ks++) {
                    uint32_t a[2][4];
                    int seg = aPl + ch * 16 + ks * 2 + (lane >> 4);
                    int rA = wm2 + (lane & 15);
                    ldm4(a[0], sSu + (uint32_t)(rA * 2048) + (uint32_t)(((seg ^ (rA & 7))) << 4));
                    int rA2 = rA + 16;
                    ldm4(a[1], sSu + (uint32_t)(rA2 * 2048) + (uint32_t)(((seg ^ (rA2 & 7))) << 4));
                    uint32_t bad = sVu + (uint32_t)(((wn2 + (lane & 7) + ((lane >> 4) << 3)) * 272
                                                    + bOff + ks * 16 + (((lane >> 3) & 1) << 3)) * 2);
                    uint32_t b4[4]; ldm4(b4, bad);
                    mmabf(c2[0][0], a[0], b4);
                    mmabf(c2[0][1], a[0], b4 + 2);
                    mmabf(c2[1][0], a[1], b4);
                    mmabf(c2[1][1], a[1], b4 + 2);
                }
            }
            __syncthreads();
        }
        int b = bh >> 3, h = bh & 7;
        #pragma unroll
        for (int ms = 0; ms < 2; ms++)
            #pragma unroll
            for (int nf = 0; nf < 2; nf++) {
                int rloc = wm2 + ms * 16 + g;
                int s0g = stile * 64 + rloc;
                int dh = wn2 + nf * 8 + tg2;
                float r0 = sRs[rloc], r1 = sRs[rloc + 8];
                __nv_bfloat16 h0, l0, h1, l1;
                split2(c2[ms][nf][0] * r0, h0, l0); split2(c2[ms][nf][1] * r0, h1, l1);
                size_t base = ((size_t)(b * 512 + s0g)) * 1024 + h * 64 + dh;
                *(uint32_t*)(ao + base)       = pk(h0, h1);
                *(uint32_t*)(ao + base + 512) = pk(l0, l1);
                split2(c2[ms][nf][2] * r1, h0, l0); split2(c2[ms][nf][3] * r1, h1, l1);
                size_t base2 = ((size_t)(b * 512 + s0g + 8)) * 1024 + h * 64 + dh;
                *(uint32_t*)(ao + base2)       = pk(h0, h1);
                *(uint32_t*)(ao + base2 + 512) = pk(l0, l1);
            }
    }
}

// ---------------- host launcher ----------------------------------------------
extern "C" void kernel_launch(void* const* d_in, const int* in_sizes, int n_in,
                              void* d_out, int out_size) {
    const float* x    = (const float*)d_in[0];
    const int*   mask = (const int*)  d_in[1];
    const float* ln_g = (const float*)d_in[2];
    const float* ln_b = (const float*)d_in[3];
    const float* lna_g= (const float*)d_in[4];
    const float* lna_b= (const float*)d_in[5];
    const float* Wq   = (const float*)d_in[6];
    const float* bq   = (const float*)d_in[7];
    const float* Wk   = (const float*)d_in[8];
    const float* bk   = (const float*)d_in[9];
    const float* Wv   = (const float*)d_in[10];
    const float* bv   = (const float*)d_in[11];
    const float* Wd   = (const float*)d_in[12];
    const float* bd   = (const float*)d_in[13];
    float* out = (float*)d_out;

    __nv_bfloat16 *ha, *wa, *qa, *ka, *vt, *ao;
    unsigned* mb;
    cudaGetSymbolAddress((void**)&ha, g_ha4);
    cudaGetSymbolAddress((void**)&wa, g_waug4);
    cudaGetSymbolAddress((void**)&qa, g_qaug4);
    cudaGetSymbolAddress((void**)&ka, g_kaug4);
    cudaGetSymbolAddress((void**)&vt, g_vt4);
    cudaGetSymbolAddress((void**)&ao, g_ao4);
    cudaGetSymbolAddress((void**)&mb, g_mb);

    const int PROJ_SM = 110592;                    // 3 x (A 18432 + B 18432)
    const int ATTN_SM = 218368;
    cudaFuncSetAttribute(gemm_qkv3, cudaFuncAttributeMaxDynamicSharedMemorySize, PROJ_SM);
    cudaFuncSetAttribute(gemm_out,  cudaFuncAttributeMaxDynamicSharedMemorySize, PROJ_SM);
    cudaFuncSetAttribute(gemm_attn, cudaFuncAttributeMaxDynamicSharedMemorySize, ATTN_SM);

    prep_ln<<<8192, 256>>>(x, ln_g, ln_b, ha);
    prep_w<<<dim3(8, 8, 4), 256>>>(Wq, Wk, Wv, Wd, wa);
    prep_mask<<<512, 256>>>(mask, mb);

    gemm_qkv3<<<dim3(4, 64, 3), 256, PROJ_SM>>>(ha, wa, bq, bk, bv, qa, ka, vt);
    gemm_attn<<<dim3(8, 128), 256, ATTN_SM>>>(qa, ka, vt, mb, lna_g, lna_b, ao);
    gemm_out<<<dim3(4, 64), 256, PROJ_SM>>>(ao, wa + 3 * 512 * 1024, bd, x, out);
}